// round 13
// baseline (speedup 1.0000x reference)
#include <cuda_runtime.h>
#include <math.h>
#include <stdint.h>

#define Xn 262144
#define Bn 64
#define Hn 256
#define THRF 1e-6f
#define NT 512
#define NMLP 64             // MLP blocks (1 batch, 8 tokens each); blocks 64..127 scan
#define TILE_FLOATS 16384   // 64KB weight tile
#define NTILES 50           // 3*16 residual tiles + 2 head tiles
#define DEPTH 2
#define CLU 4

typedef unsigned long long ull;

__device__ __forceinline__ float gelu_f(float v) {
    return 0.5f * v * (1.0f + erff(v * 0.70710678118654752f));
}
__device__ __forceinline__ void ffma2(ull& d, ull a, ull b) {
    asm("fma.rn.f32x2 %0, %1, %2, %0;" : "+l"(d) : "l"(a), "l"(b));
}
__device__ __forceinline__ ull addf2(ull a, ull b) {
    ull r; asm("add.rn.f32x2 %0, %1, %2;" : "=l"(r) : "l"(a), "l"(b)); return r;
}
__device__ __forceinline__ ull dup2(float v) {
    ull r; asm("mov.b64 %0, {%1, %1};" : "=l"(r) : "f"(v)); return r;
}
__device__ __forceinline__ float2 unpk(ull v) {
    float2 f; asm("mov.b64 {%0, %1}, %2;" : "=f"(f.x), "=f"(f.y) : "l"(v)); return f;
}
__device__ __forceinline__ uint32_t smem_u32(const void* p) {
    return (uint32_t)__cvta_generic_to_shared(p);
}
__device__ __forceinline__ void lds128(ull& a, ull& b, const ull* p) {
    uint32_t addr = smem_u32(p);
    asm volatile("ld.shared.v2.u64 {%0, %1}, [%2];" : "=l"(a), "=l"(b) : "r"(addr));
}
__device__ __forceinline__ void sts128(ull* p, ull a, ull b) {
    uint32_t addr = smem_u32(p);
    asm volatile("st.shared.v2.u64 [%0], {%1, %2};" :: "r"(addr), "l"(a), "l"(b) : "memory");
}

#define MBAR_INIT(addr, cnt) \
    asm volatile("mbarrier.init.shared.b64 [%0], %1;" :: "r"(addr), "r"(cnt) : "memory")
#define MBAR_EXPECT_TX(addr, bytes) \
    asm volatile("mbarrier.arrive.expect_tx.shared.b64 _, [%0], %1;" :: "r"(addr), "r"(bytes) : "memory")
#define MBAR_ARRIVE_CLUSTER(addr, rk) \
    asm volatile("{\n\t.reg .b32 ra%=;\n\tmapa.shared::cluster.u32 ra%=, %0, %1;\n\t" \
                 "mbarrier.arrive.shared::cluster.b64 _, [ra%=];\n\t}" \
                 :: "r"(addr), "r"(rk) : "memory")

__device__ __forceinline__ void mbar_wait(uint32_t addr, uint32_t parity) {
    asm volatile(
        "{\n\t.reg .pred P%=;\n\t"
        "WL%=:\n\t"
        "mbarrier.try_wait.parity.acquire.cta.shared::cta.b64 P%=, [%0], %1, 0x989680;\n\t"
        "@!P%= bra WL%=;\n\t}"
        :: "r"(addr), "r"(parity) : "memory");
}
__device__ __forceinline__ void bulk_mcast(uint32_t dst, const float* src, uint32_t mbar) {
    asm volatile(
        "cp.async.bulk.shared::cluster.global.mbarrier::complete_tx::bytes.multicast::cluster"
        " [%0], [%1], %2, [%3], %4;"
        :: "r"(dst), "l"(src), "r"(16384u), "r"(mbar), "h"((unsigned short)0xF)
        : "memory");
}
#define CLUSTER_SYNC_() do { \
    asm volatile("barrier.cluster.arrive.aligned;" ::: "memory"); \
    asm volatile("barrier.cluster.wait.aligned;" ::: "memory"); \
} while (0)

__global__ void __launch_bounds__(NT, 1) __cluster_dims__(CLU, 1, 1) fused_all(
    const float* __restrict__ x,
    const float* __restrict__ w_in,  const float* __restrict__ b_in,
    const float* __restrict__ ln_in_g, const float* __restrict__ ln_in_b,
    const float* __restrict__ rb_ln_g, const float* __restrict__ rb_ln_b,
    const float* __restrict__ rb_w1,  const float* __restrict__ rb_b1,
    const float* __restrict__ rb_w2,  const float* __restrict__ rb_b2,
    const float* __restrict__ out_ln_g, const float* __restrict__ out_ln_b,
    const float* __restrict__ out_w1, const float* __restrict__ out_b1,
    const float* __restrict__ out_w2, const float* __restrict__ out_b2,
    float* __restrict__ out)
{
    const int tid = threadIdx.x;

    // ================= SCAN BLOCKS (64..127): one full density row =================
    if (blockIdx.x >= NMLP) {
        int sb = blockIdx.x - NMLP;
        const float* dd = x + (size_t)sb * 2 * Xn;
        const float4* d4 = (const float4*)dd;
        __shared__ int cw[16];
        int cnt = 0;
        #pragma unroll 4
        for (int it = 0; it < Xn / 4 / NT; it++) {   // 128 iters
            int i4 = tid + it * NT;
            float4 v = __ldcs(&d4[i4]);
            int j0 = i4 << 2;
            bool cross = (j0 + 4) < Xn;
            float nxt = __shfl_down_sync(0xffffffffu, v.x, 1);
            if ((tid & 31) == 31)
                nxt = cross ? __ldcs(&dd[j0 + 4]) : 0.f;
            cnt += (fabsf(v.x - v.y) > THRF);
            cnt += (fabsf(v.y - v.z) > THRF);
            cnt += (fabsf(v.z - v.w) > THRF);
            cnt += (cross && (fabsf(v.w - nxt) > THRF));
        }
        #pragma unroll
        for (int o = 16; o; o >>= 1) cnt += __shfl_xor_sync(0xffffffffu, cnt, o);
        if ((tid & 31) == 0) cw[tid >> 5] = cnt;
        __syncthreads();
        if (tid == 0) {
            int s = 0;
            #pragma unroll
            for (int w = 0; w < 16; w++) s += cw[w];
            out[Bn * 48 + sb] = (float)s;
        }
        return;
    }

    // ================= MLP BLOCKS (0..63): batch b, 8 tokens, 16 warps =================
    const uint32_t rank = (uint32_t)(blockIdx.x & 3);
    const int b = blockIdx.x;
    const float* d  = x + (size_t)b * 2 * Xn;
    const float* cr = d + Xn;

    extern __shared__ float smem[];
    float* ringf = smem;                                  // 32768 f (128 KB)
    float* s_h   = smem + DEPTH * TILE_FLOATS;            // 2048 f [t*256+c]
    ull*   s_ztd = (ull*)(s_h + 2048);                    // 2048 ull dup z [k*8+t] (16 KB)
    ull*   s_zzd = (ull*)(s_h + 2048 + 4096);             // 4096 ull dup zz [k*8+t] (32 KB)
    float* s_zp  = (float*)s_zzd;                         //   overlay: 2048 f plain z (head)
    float* s_a1  = ((float*)s_zzd) + 2048;                //   overlay: 1024 f a1 [t*128+c]
    ull*   s_rd  = (ull*)(s_h + 2048 + 4096 + 8192);      // 3072 ull scratch (24 KB)
    float* s_rdf = (float*)s_rd;

    __shared__ uint64_t mb_full[DEPTH], mb_empty[DEPTH];
    __shared__ const float* s_tiles[NTILES];
    __shared__ float s_mu[8], s_rs[8];
    __shared__ float s_tk[2][8];
    __shared__ unsigned s_wm[16], s_vm[16];
    __shared__ int s_idx[8], s_non[8];
    __shared__ int s_nd, s_nn, s_done;

    const uint32_t slot_base = smem_u32(smem);
    uint32_t mbf[DEPTH], mbe[DEPTH];
    #pragma unroll
    for (int s = 0; s < DEPTH; s++) {
        mbf[s] = smem_u32(&mb_full[s]);
        mbe[s] = smem_u32(&mb_empty[s]);
    }

    if (tid == 0) {
        #pragma unroll
        for (int s = 0; s < DEPTH; s++) {
            MBAR_INIT(mbf[s], 1u);
            MBAR_INIT(mbe[s], 4u);
        }
        s_nd = 0; s_nn = 0; s_done = 0;
    }
    if (tid < NTILES) {
        int j = tid;
        const float* p;
        if (j < 48) {
            int ph = j >> 4, w = j & 15;
            p = (w < 8) ? rb_w1 + (size_t)ph * 131072 + (size_t)w * TILE_FLOATS
                        : rb_w2 + (size_t)ph * 131072 + (size_t)(w - 8) * TILE_FLOATS;
        } else {
            p = out_w1 + (size_t)(j - 48) * TILE_FLOATS;
        }
        s_tiles[j] = p;
    }
    __syncthreads();
    CLUSTER_SYNC_();

    int gt = 0;
    #define TILE_ISSUE()                                                          \
        if (gt < NTILES) {                                                        \
            if (tid == 0) {                                                       \
                int ss = gt % DEPTH;                                              \
                mbar_wait(mbe[ss], (uint32_t)(((gt / DEPTH) & 1) ^ 1));           \
                MBAR_EXPECT_TX(mbf[ss], 65536u);                                  \
                bulk_mcast(slot_base + (uint32_t)ss * 65536u + rank * 16384u,     \
                           s_tiles[gt] + rank * 4096, mbf[ss]);                   \
            }                                                                     \
            gt++;                                                                 \
        }
    #define TILE_RELEASE(jglob)                                                   \
        __syncthreads();                                                          \
        if (tid == 0) {                                                           \
            int ss = (jglob) % DEPTH;                                             \
            MBAR_ARRIVE_CLUSTER(mbe[ss], 0u);                                     \
            MBAR_ARRIVE_CLUSTER(mbe[ss], 1u);                                     \
            MBAR_ARRIVE_CLUSTER(mbe[ss], 2u);                                     \
            MBAR_ARRIVE_CLUSTER(mbe[ss], 3u);                                     \
        }

    // prime both ring slots (land during front-find)
    TILE_ISSUE();
    TILE_ISSUE();

    // ---- find first 8 discontinuities (ordered), 512-wide chunks ----
    for (int base = 0; base < Xn - 1; base += NT) {
        int i = base + tid;
        bool valid = (i < Xn - 1);
        bool disc = valid && (fabsf(d[i] - d[i + 1]) > THRF);
        unsigned m  = __ballot_sync(0xffffffffu, disc);
        unsigned vm = __ballot_sync(0xffffffffu, valid);
        if ((tid & 31) == 0) { s_wm[tid >> 5] = m; s_vm[tid >> 5] = vm; }
        __syncthreads();
        if (tid == 0) {
            for (int w = 0; w < 16 && s_nd < 8; w++) {
                unsigned mm = s_wm[w], vv = s_vm[w];
                int ib = base + w * 32;
                while (vv) {
                    int lane = __ffs(vv) - 1;
                    vv &= vv - 1;
                    int idx = ib + lane;
                    if ((mm >> lane) & 1u) {
                        if (s_nd < 8) {
                            s_idx[s_nd++] = idx;
                            if (s_nd >= 8) break;
                        }
                    } else {
                        if (s_nn < 8) s_non[s_nn++] = idx;
                    }
                }
            }
            if (s_nd >= 8) s_done = 1;
        }
        __syncthreads();
        if (s_done) break;
    }
    if (tid < 8) {
        int k = tid;
        int nd = s_nd;
        int i; float vf;
        if (k < nd) { i = s_idx[k]; vf = 1.0f; }
        else        { i = s_non[k - nd]; vf = 0.0f; }
        float uL = d[i], uR = d[i + 1];
        float fc = 0.5f * (cr[i] + cr[i + 1]);
        s_tk[0][k] = uL;
        s_tk[1][k] = uR;
        int base = b * 48;
        out[base + 16 + k] = uL;
        out[base + 24 + k] = uR;
        out[base + 32 + k] = fc;
        out[base + 40 + k] = vf;
    }
    __syncthreads();

    // ---- LN stats over 8 tokens (warps 0-7 reduce token w from s_h[t*256+c]) ----
    #define LN8(buf)                                                              \
    {                                                                             \
        int w = tid >> 5, lane = tid & 31;                                        \
        if (w < 8) {                                                              \
            float s1 = 0.f, s2 = 0.f;                                             \
            _Pragma("unroll")                                                     \
            for (int j = 0; j < 8; j++) {                                         \
                float v = (buf)[w * 256 + lane + 32 * j];                         \
                s1 += v;                                                          \
                s2 = fmaf(v, v, s2);                                              \
            }                                                                     \
            _Pragma("unroll")                                                     \
            for (int o = 16; o; o >>= 1) {                                        \
                s1 += __shfl_xor_sync(0xffffffffu, s1, o);                        \
                s2 += __shfl_xor_sync(0xffffffffu, s2, o);                        \
            }                                                                     \
            if (lane == 0) {                                                      \
                float mu = s1 * (1.f / 256.f);                                    \
                float var = fmaxf(s2 * (1.f / 256.f) - mu * mu, 0.f);             \
                s_mu[w] = mu;                                                     \
                s_rs[w] = rsqrtf(var + 1e-5f);                                    \
            }                                                                     \
        }                                                                         \
        __syncthreads();                                                          \
    }

    // ---- input layer ----
    float pre[8];
    if (tid < Hn) {
        int n = tid;
        float wv[6];
        #pragma unroll
        for (int f = 0; f < 6; f++) wv[f] = w_in[f * Hn + n];
        float bi = b_in[n];
        #pragma unroll
        for (int t = 0; t < 8; t++) {
            float uL = s_tk[0][t], uR = s_tk[1][t];
            float df = uL - uR;
            float sg = (df > 0.f) ? 1.f : ((df < 0.f) ? -1.f : 0.f);
            float p = bi;
            p = fmaf(uL, wv[0], p);
            p = fmaf(uR, wv[1], p);
            p = fmaf(df, wv[2], p);
            p = fmaf(fabsf(df), wv[3], p);
            p = fmaf(0.5f * (uL + uR), wv[4], p);
            p = fmaf(sg, wv[5], p);
            pre[t] = p;
            s_h[t * 256 + n] = p;
        }
    }
    __syncthreads();
    LN8(s_h);
    if (tid < Hn) {
        float lg = ln_in_g[tid], lb = ln_in_b[tid];
        #pragma unroll
        for (int t = 0; t < 8; t++)
            s_h[t * 256 + tid] = gelu_f((pre[t] - s_mu[t]) * s_rs[t] * lg + lb);
    }
    __syncthreads();

    // ---- 3 residual blocks ----
    for (int i = 0; i < 3; i++) {
        LN8(s_h);
        // ztd write: thread (c = tid>>1, h = tid&1) covers tokens 4h..4h+3
        {
            int c = tid >> 1, h = tid & 1;
            float g = rb_ln_g[i * Hn + c], bb = rb_ln_b[i * Hn + c];
            ull zd[4];
            #pragma unroll
            for (int t4 = 0; t4 < 4; t4++) {
                int t = 4 * h + t4;
                float v = s_h[t * 256 + c];
                zd[t4] = dup2((v - s_mu[t]) * s_rs[t] * g + bb);
            }
            sts128(&s_ztd[c * 8 + 4 * h], zd[0], zd[1]);
            sts128(&s_ztd[c * 8 + 4 * h + 2], zd[2], zd[3]);
        }
        __syncthreads();

        // ===== GEMM1: thread (ks = tid>>8, cg = tid&255) -> cols 2cg,2cg+1 =====
        {
            const int cg = tid & 255, ks = tid >> 8;
            ull acc[8];
            #pragma unroll
            for (int t = 0; t < 8; t++) acc[t] = 0ull;
            #pragma unroll
            for (int t8 = 0; t8 < 8; t8++) {
                int jglob = i * 16 + t8;
                mbar_wait(mbf[jglob % DEPTH], (uint32_t)((jglob / DEPTH) & 1));
                const float* cur = ringf + (jglob % DEPTH) * TILE_FLOATS;
                #pragma unroll
                for (int kk = 0; kk < 16; kk++) {
                    int kl = ks * 16 + kk;
                    int kg = t8 * 32 + kl;
                    ull w01 = *(const ull*)(cur + kl * 512 + 2 * cg);
                    ull z0, z1, z2, z3, z4, z5, z6, z7;
                    lds128(z0, z1, &s_ztd[kg * 8 + 0]);
                    lds128(z2, z3, &s_ztd[kg * 8 + 2]);
                    lds128(z4, z5, &s_ztd[kg * 8 + 4]);
                    lds128(z6, z7, &s_ztd[kg * 8 + 6]);
                    ffma2(acc[0], w01, z0); ffma2(acc[1], w01, z1);
                    ffma2(acc[2], w01, z2); ffma2(acc[3], w01, z3);
                    ffma2(acc[4], w01, z4); ffma2(acc[5], w01, z5);
                    ffma2(acc[6], w01, z6); ffma2(acc[7], w01, z7);
                }
                TILE_RELEASE(jglob);
                TILE_ISSUE();
            }
            if (ks == 1) {
                #pragma unroll
                for (int t = 0; t < 8; t++)
                    s_rd[t * 256 + cg] = acc[t];
            }
            float2 b1v = make_float2(0.f, 0.f);
            if (ks == 0) b1v = *(const float2*)(rb_b1 + i * 512 + 2 * cg);
            __syncthreads();
            if (ks == 0) {
                #pragma unroll
                for (int t = 0; t < 8; t++) {
                    float2 u = unpk(addf2(acc[t], s_rd[t * 256 + cg]));
                    s_zzd[(2 * cg + 0) * 8 + t] = dup2(gelu_f(u.x + b1v.x));
                    s_zzd[(2 * cg + 1) * 8 + t] = dup2(gelu_f(u.y + b1v.y));
                }
            }
            __syncthreads();
        }

        // ===== GEMM2: thread (ks4 = tid>>7, cg = tid&127) -> cols 2cg,2cg+1 =====
        {
            const int cg = tid & 127, ks4 = tid >> 7;
            ull acc[8];
            #pragma unroll
            for (int t = 0; t < 8; t++) acc[t] = 0ull;
            #pragma unroll
            for (int t8 = 0; t8 < 8; t8++) {
                int jglob = i * 16 + 8 + t8;
                mbar_wait(mbf[jglob % DEPTH], (uint32_t)((jglob / DEPTH) & 1));
                const float* cur = ringf + (jglob % DEPTH) * TILE_FLOATS;
                #pragma unroll
                for (int kk = 0; kk < 16; kk++) {
                    int kl = ks4 * 16 + kk;
                    int kg = t8 * 64 + kl;
                    ull w01 = *(const ull*)(cur + kl * 256 + 2 * cg);
                    ull z0, z1, z2, z3, z4, z5, z6, z7;
                    lds128(z0, z1, &s_zzd[kg * 8 + 0]);
                    lds128(z2, z3, &s_zzd[kg * 8 + 2]);
                    lds128(z4, z5, &s_zzd[kg * 8 + 4]);
                    lds128(z6, z7, &s_zzd[kg * 8 + 6]);
                    ffma2(acc[0], w01, z0); ffma2(acc[1], w01, z1);
                    ffma2(acc[2], w01, z2); ffma2(acc[3], w01, z3);
                    ffma2(acc[4], w01, z4); ffma2(acc[5], w01, z5);
                    ffma2(acc[6], w01, z6); ffma2(acc[7], w01, z7);
                }
                TILE_RELEASE(jglob);
                TILE_ISSUE();
            }
            if (ks4 > 0) {
                int km = ks4 - 1;
                #pragma unroll
                for (int t = 0; t < 8; t++)
                    s_rd[(km * 8 + t) * 128 + cg] = acc[t];
            }
            float2 b2v = make_float2(0.f, 0.f);
            if (ks4 == 0) b2v = *(const float2*)(rb_b2 + i * 256 + 2 * cg);
            __syncthreads();
            if (ks4 == 0) {
                #pragma unroll
                for (int t = 0; t < 8; t++) {
                    ull a = acc[t];
                    a = addf2(a, s_rd[(0 * 8 + t) * 128 + cg]);
                    a = addf2(a, s_rd[(1 * 8 + t) * 128 + cg]);
                    a = addf2(a, s_rd[(2 * 8 + t) * 128 + cg]);
                    float2 u = unpk(a);
                    s_h[t * 256 + 2 * cg + 0] += u.x + b2v.x;
                    s_h[t * 256 + 2 * cg + 1] += u.y + b2v.y;
                }
            }
            __syncthreads();
        }
    }

    // ---- output head ----
    LN8(s_h);
    {
        int c = tid >> 1, h = tid & 1;
        float og = out_ln_g[c], ob = out_ln_b[c];
        float4 zv;
        float* zvp = (float*)&zv;
        #pragma unroll
        for (int t4 = 0; t4 < 4; t4++) {
            int t = 4 * h + t4;
            float v = s_h[t * 256 + c];
            zvp[t4] = (v - s_mu[t]) * s_rs[t] * og + ob;
        }
        *(float4*)&s_zp[c * 8 + 4 * h] = zv;
    }
    __syncthreads();

    // a1 = gelu(z @ out_w1 + b1): thread (ks4, cg=col), rows ks4*32..+32 per 128-row tile
    {
        const int cg = tid & 127, ks4 = tid >> 7;
        float a[8] = {0.f, 0.f, 0.f, 0.f, 0.f, 0.f, 0.f, 0.f};
        #pragma unroll
        for (int t8 = 0; t8 < 2; t8++) {
            int jglob = 48 + t8;
            mbar_wait(mbf[jglob % DEPTH], (uint32_t)((jglob / DEPTH) & 1));
            const float* cur = ringf + (jglob % DEPTH) * TILE_FLOATS;
            #pragma unroll 8
            for (int kk = 0; kk < 32; kk++) {
                int kl = ks4 * 32 + kk;
                int kg = t8 * 128 + kl;
                float w = cur[kl * 128 + cg];
                float4 za = *(const float4*)&s_zp[kg * 8 + 0];
                float4 zb = *(const float4*)&s_zp[kg * 8 + 4];
                a[0] = fmaf(za.x, w, a[0]);
                a[1] = fmaf(za.y, w, a[1]);
                a[2] = fmaf(za.z, w, a[2]);
                a[3] = fmaf(za.w, w, a[3]);
                a[4] = fmaf(zb.x, w, a[4]);
                a[5] = fmaf(zb.y, w, a[5]);
                a[6] = fmaf(zb.z, w, a[6]);
                a[7] = fmaf(zb.w, w, a[7]);
            }
            TILE_RELEASE(jglob);
        }
        if (ks4 > 0) {
            int km = ks4 - 1;
            #pragma unroll
            for (int t = 0; t < 8; t++)
                s_rdf[(km * 8 + t) * 128 + cg] = a[t];
        }
        float bo = 0.f;
        if (ks4 == 0) bo = out_b1[cg];
        __syncthreads();
        if (ks4 == 0) {
            #pragma unroll
            for (int t = 0; t < 8; t++) {
                float s = a[t]
                        + s_rdf[(0 * 8 + t) * 128 + cg]
                        + s_rdf[(1 * 8 + t) * 128 + cg]
                        + s_rdf[(2 * 8 + t) * 128 + cg];
                s_a1[t * 128 + cg] = gelu_f(s + bo);
            }
        }
        __syncthreads();
    }

    // speed = a1 @ out_w2 + out_b2: warp w (0..15) -> (token w>>1, col w&1)
    {
        int w = tid >> 5, lane = tid & 31;
        int t = w >> 1, cc = w & 1;
        float s = 0.f;
        s = fmaf(s_a1[t * 128 + lane],      out_w2[lane * 2 + cc],        s);
        s = fmaf(s_a1[t * 128 + lane + 32], out_w2[(lane + 32) * 2 + cc], s);
        s = fmaf(s_a1[t * 128 + lane + 64], out_w2[(lane + 64) * 2 + cc], s);
        s = fmaf(s_a1[t * 128 + lane + 96], out_w2[(lane + 96) * 2 + cc], s);
        #pragma unroll
        for (int o = 16; o; o >>= 1) s += __shfl_xor_sync(0xffffffffu, s, o);
        if (lane == 0)
            out[b * 48 + cc * 8 + t] = s + out_b2[cc];
    }

    CLUSTER_SYNC_();
}

extern "C" void kernel_launch(void* const* d_in, const int* in_sizes, int n_in,
                              void* d_out, int out_size) {
    const float* x        = (const float*)d_in[0];
    const float* w_in     = (const float*)d_in[1];
    const float* b_in     = (const float*)d_in[2];
    const float* ln_in_g  = (const float*)d_in[3];
    const float* ln_in_b  = (const float*)d_in[4];
    const float* rb_ln_g  = (const float*)d_in[5];
    const float* rb_ln_b  = (const float*)d_in[6];
    const float* rb_w1    = (const float*)d_in[7];
    const float* rb_b1    = (const float*)d_in[8];
    const float* rb_w2    = (const float*)d_in[9];
    const float* rb_b2    = (const float*)d_in[10];
    const float* out_ln_g = (const float*)d_in[11];
    const float* out_ln_b = (const float*)d_in[12];
    const float* out_w1   = (const float*)d_in[13];
    const float* out_b1   = (const float*)d_in[14];
    const float* out_w2   = (const float*)d_in[15];
    const float* out_b2   = (const float*)d_in[16];
    float* out = (float*)d_out;

    // ring(128KB) + s_h(8KB) + ztd(16KB) + zzd(32KB) + scratch(24KB) = 208KB
    const int smem_bytes = DEPTH * TILE_FLOATS * 4 + 8192 + 16384 + 32768 + 24576;
    cudaFuncSetAttribute(fused_all, cudaFuncAttributeMaxDynamicSharedMemorySize, smem_bytes);

    fused_all<<<128, NT, smem_bytes>>>(x, w_in, b_in, ln_in_g, ln_in_b,
                                       rb_ln_g, rb_ln_b, rb_w1, rb_b1, rb_w2, rb_b2,
                                       out_ln_g, out_ln_b, out_w1, out_b1, out_w2, out_b2,
                                       out);
}

// round 14
// speedup vs baseline: 1.2978x; 1.2978x over previous
#include <cuda_runtime.h>
#include <math.h>
#include <stdint.h>

#define Xn 262144
#define Bn 64
#define Hn 256
#define THRF 1e-6f
#define NT 512
#define TILE_FLOATS 16384   // 64KB weight tile
#define NTILES 50           // 3*16 residual tiles + 2 head tiles
#define DEPTH 3
#define CLU 4

typedef unsigned long long ull;

// 2-party count handshake (zero-init; reset each run -> replay safe)
__device__ int g_part[Bn][2];
__device__ unsigned g_flag[Bn];

__device__ __forceinline__ float gelu_f(float v) {
    return 0.5f * v * (1.0f + erff(v * 0.70710678118654752f));
}
__device__ __forceinline__ void ffma2(ull& d, ull a, ull b) {
    asm("fma.rn.f32x2 %0, %1, %2, %0;" : "+l"(d) : "l"(a), "l"(b));
}
__device__ __forceinline__ ull addf2(ull a, ull b) {
    ull r; asm("add.rn.f32x2 %0, %1, %2;" : "=l"(r) : "l"(a), "l"(b)); return r;
}
__device__ __forceinline__ ull dup2(float v) {
    ull r; asm("mov.b64 %0, {%1, %1};" : "=l"(r) : "f"(v)); return r;
}
__device__ __forceinline__ float2 unpk(ull v) {
    float2 f; asm("mov.b64 {%0, %1}, %2;" : "=f"(f.x), "=f"(f.y) : "l"(v)); return f;
}
__device__ __forceinline__ uint32_t smem_u32(const void* p) {
    return (uint32_t)__cvta_generic_to_shared(p);
}
// 16-byte shared load as two ulls
__device__ __forceinline__ void lds128(ull& a, ull& b, const ull* p) {
    uint32_t addr = smem_u32(p);
    asm volatile("ld.shared.v2.u64 {%0, %1}, [%2];" : "=l"(a), "=l"(b) : "r"(addr));
}

#define MBAR_INIT(addr, cnt) \
    asm volatile("mbarrier.init.shared.b64 [%0], %1;" :: "r"(addr), "r"(cnt) : "memory")
#define MBAR_EXPECT_TX(addr, bytes) \
    asm volatile("mbarrier.arrive.expect_tx.shared.b64 _, [%0], %1;" :: "r"(addr), "r"(bytes) : "memory")
#define MBAR_ARRIVE_CLUSTER(addr, rk) \
    asm volatile("{\n\t.reg .b32 ra%=;\n\tmapa.shared::cluster.u32 ra%=, %0, %1;\n\t" \
                 "mbarrier.arrive.shared::cluster.b64 _, [ra%=];\n\t}" \
                 :: "r"(addr), "r"(rk) : "memory")

__device__ __forceinline__ void mbar_wait(uint32_t addr, uint32_t parity) {
    asm volatile(
        "{\n\t.reg .pred P%=;\n\t"
        "WL%=:\n\t"
        "mbarrier.try_wait.parity.acquire.cta.shared::cta.b64 P%=, [%0], %1, 0x989680;\n\t"
        "@!P%= bra WL%=;\n\t}"
        :: "r"(addr), "r"(parity) : "memory");
}
__device__ __forceinline__ void bulk_mcast(uint32_t dst, const float* src, uint32_t mbar) {
    asm volatile(
        "cp.async.bulk.shared::cluster.global.mbarrier::complete_tx::bytes.multicast::cluster"
        " [%0], [%1], %2, [%3], %4;"
        :: "r"(dst), "l"(src), "r"(16384u), "r"(mbar), "h"((unsigned short)0xF)
        : "memory");
}
#define CLUSTER_SYNC_() do { \
    asm volatile("barrier.cluster.arrive.aligned;" ::: "memory"); \
    asm volatile("barrier.cluster.wait.aligned;" ::: "memory"); \
} while (0)

#define BARM() asm volatile("bar.sync 1, 256;" ::: "memory")
#define BARS() asm volatile("bar.sync 2, 256;" ::: "memory")

// LN stats over token-interleaved buffer: (col c, token t) at buf[(c*4+t)*stride]
__device__ __forceinline__ void ln_stats_m(const float* buf, int stride,
                                           float* s_mu, float* s_rs, int tid) {
    int w = tid >> 5, lane = tid & 31;
    if (w < 4) {
        float s1 = 0.f, s2 = 0.f;
        #pragma unroll
        for (int j = 0; j < 8; j++) {
            float v = buf[((lane + 32 * j) * 4 + w) * stride];
            s1 += v;
            s2 = fmaf(v, v, s2);
        }
        #pragma unroll
        for (int o = 16; o; o >>= 1) {
            s1 += __shfl_xor_sync(0xffffffffu, s1, o);
            s2 += __shfl_xor_sync(0xffffffffu, s2, o);
        }
        if (lane == 0) {
            float mu = s1 * (1.f / 256.f);
            float var = fmaxf(s2 * (1.f / 256.f) - mu * mu, 0.f);
            s_mu[w] = mu;
            s_rs[w] = rsqrtf(var + 1e-5f);
        }
    }
    BARM();
}

__global__ void __launch_bounds__(NT, 1) __cluster_dims__(CLU, 1, 1) fused_all(
    const float* __restrict__ x,
    const float* __restrict__ w_in,  const float* __restrict__ b_in,
    const float* __restrict__ ln_in_g, const float* __restrict__ ln_in_b,
    const float* __restrict__ rb_ln_g, const float* __restrict__ rb_ln_b,
    const float* __restrict__ rb_w1,  const float* __restrict__ rb_b1,
    const float* __restrict__ rb_w2,  const float* __restrict__ rb_b2,
    const float* __restrict__ out_ln_g, const float* __restrict__ out_ln_b,
    const float* __restrict__ out_w1, const float* __restrict__ out_b1,
    const float* __restrict__ out_w2, const float* __restrict__ out_b2,
    float* __restrict__ out)
{
    const int tid  = threadIdx.x;
    const uint32_t rank = (uint32_t)(blockIdx.x & 3);
    const int b     = blockIdx.x >> 1;
    const int half  = blockIdx.x & 1;
    const int kbase = half * 4;
    const float* d  = x + (size_t)b * 2 * Xn;
    const float* cr = d + Xn;

    extern __shared__ float smem[];
    float* ringf = smem;                                  // 3*16384 f (192 KB)
    float* s_h   = smem + DEPTH * TILE_FLOATS;            // 1024 f [col*4+t]
    ull*   s_ztd = (ull*)(s_h + 1024);                    // region B: 1024 ull dup z (8 KB)
    ull*   s_rd  = s_ztd;                                 //   overlay: reduction scratch
    float* s_rdf = (float*)s_rd;
    ull*   s_zzd = (ull*)(s_h + 1024 + 2048);             // region A: 2048 ull dup zz (16 KB)
    float* s_zp  = (float*)s_zzd;                         //   overlay: 1024 f plain z (head)
    float* s_a1  = ((float*)s_zzd) + 1024;                //   overlay: 1024 f a1 (head)

    __shared__ uint64_t mb_full[DEPTH], mb_empty[DEPTH];
    __shared__ const float* s_tiles[NTILES];
    __shared__ float s_mu[4], s_rs[4];
    __shared__ float s_tk[2][4];
    __shared__ unsigned s_wm[8], s_vm[8];
    __shared__ int s_idx[8], s_non[8];
    __shared__ int s_nd, s_nn, s_done;
    __shared__ int cw[8];

    const uint32_t slot_base = smem_u32(smem);
    uint32_t mbf[DEPTH], mbe[DEPTH];
    #pragma unroll
    for (int s = 0; s < DEPTH; s++) {
        mbf[s] = smem_u32(&mb_full[s]);
        mbe[s] = smem_u32(&mb_empty[s]);
    }

    if (tid == 0) {
        #pragma unroll
        for (int s = 0; s < DEPTH; s++) {
            MBAR_INIT(mbf[s], 1u);
            MBAR_INIT(mbe[s], 4u);
        }
        s_nd = 0; s_nn = 0; s_done = 0;
    }
    if (tid < NTILES) {
        int j = tid;
        const float* p;
        if (j < 48) {
            int ph = j >> 4, w = j & 15;
            p = (w < 8) ? rb_w1 + (size_t)ph * 131072 + (size_t)w * TILE_FLOATS
                        : rb_w2 + (size_t)ph * 131072 + (size_t)(w - 8) * TILE_FLOATS;
        } else {
            p = out_w1 + (size_t)(j - 48) * TILE_FLOATS;
        }
        s_tiles[j] = p;
    }
    __syncthreads();
    CLUSTER_SYNC_();

    int gt = 0;
    #define TILE_ISSUE()                                                          \
        if (gt < NTILES) {                                                        \
            if (tid == 0) {                                                       \
                int ss = gt % DEPTH;                                              \
                mbar_wait(mbe[ss], (uint32_t)(((gt / DEPTH) & 1) ^ 1));           \
                MBAR_EXPECT_TX(mbf[ss], 65536u);                                  \
                bulk_mcast(slot_base + (uint32_t)ss * 65536u + rank * 16384u,     \
                           s_tiles[gt] + rank * 4096, mbf[ss]);                   \
            }                                                                     \
            gt++;                                                                 \
        }
    #define TILE_RELEASE(jglob)                                                   \
        BARM();                                                                   \
        if (tid == 0) {                                                           \
            int ss = (jglob) % DEPTH;                                             \
            MBAR_ARRIVE_CLUSTER(mbe[ss], 0u);                                     \
            MBAR_ARRIVE_CLUSTER(mbe[ss], 1u);                                     \
            MBAR_ARRIVE_CLUSTER(mbe[ss], 2u);                                     \
            MBAR_ARRIVE_CLUSTER(mbe[ss], 3u);                                     \
        }

    // prime TWO tiles only: per-tile issue then keeps gt = j+2 while processing
    // tile j, so the empty-wait targets the slot last held by tile j-1 -> one
    // full tile of cross-CTA skew slack at DEPTH=3.
    TILE_ISSUE();
    TILE_ISSUE();

    if (tid >= 256) {
        // ================= SCAN WARPS (8-15): count this half-row =================
        int stid = tid - 256;
        const float4* d4 = (const float4*)d;
        const int start4 = (half * (Xn / 2)) >> 2;
        const int iend   = half ? (Xn - 1) : (Xn / 2);
        int cnt = 0;
        #pragma unroll 4
        for (int it = 0; it < (Xn / 2) / (256 * 4); it++) {
            int i4 = start4 + stid + it * 256;
            float4 v = __ldcs(&d4[i4]);
            int j0 = i4 << 2;
            bool cross = (j0 + 3) < iend;
            float nxt = __shfl_down_sync(0xffffffffu, v.x, 1);
            if ((stid & 31) == 31)
                nxt = cross ? __ldcs(&d[j0 + 4]) : 0.f;
            cnt += (fabsf(v.x - v.y) > THRF);
            cnt += (fabsf(v.y - v.z) > THRF);
            cnt += (fabsf(v.z - v.w) > THRF);
            cnt += (cross && (fabsf(v.w - nxt) > THRF));
        }
        #pragma unroll
        for (int o = 16; o; o >>= 1) cnt += __shfl_xor_sync(0xffffffffu, cnt, o);
        if ((stid & 31) == 0) cw[stid >> 5] = cnt;
        BARS();
        if (stid == 0) {
            int s = 0;
            #pragma unroll
            for (int w = 0; w < 8; w++) s += cw[w];
            g_part[b][half] = s;
            __threadfence();
            unsigned old = atomicAdd(&g_flag[b], 1u);
            if (old == 1u) {
                out[Bn * 48 + b] = (float)(s + g_part[b][half ^ 1]);
                g_flag[b] = 0u;
            }
        }
    } else {
        // ================= MLP WARPS (0-7): front-find + network =================

        // ---- find first 8 discontinuities (ordered), 256-wide chunks ----
        for (int base = 0; base < Xn - 1; base += 256) {
            int i = base + tid;
            bool valid = (i < Xn - 1);
            bool disc = valid && (fabsf(d[i] - d[i + 1]) > THRF);
            unsigned m  = __ballot_sync(0xffffffffu, disc);
            unsigned vm = __ballot_sync(0xffffffffu, valid);
            if ((tid & 31) == 0) { s_wm[tid >> 5] = m; s_vm[tid >> 5] = vm; }
            BARM();
            if (tid == 0) {
                for (int w = 0; w < 8 && s_nd < 8; w++) {
                    unsigned mm = s_wm[w], vv = s_vm[w];
                    int ib = base + w * 32;
                    while (vv) {
                        int lane = __ffs(vv) - 1;
                        vv &= vv - 1;
                        int idx = ib + lane;
                        if ((mm >> lane) & 1u) {
                            if (s_nd < 8) {
                                s_idx[s_nd++] = idx;
                                if (s_nd >= 8) break;
                            }
                        } else {
                            if (s_nn < 8) s_non[s_nn++] = idx;
                        }
                    }
                }
                if (s_nd >= 8) s_done = 1;
            }
            BARM();
            if (s_done) break;
        }
        if (tid < 4) {
            int k = kbase + tid;
            int nd = s_nd;
            int i; float vf;
            if (k < nd) { i = s_idx[k]; vf = 1.0f; }
            else        { i = s_non[k - nd]; vf = 0.0f; }
            float uL = d[i], uR = d[i + 1];
            float fc = 0.5f * (cr[i] + cr[i + 1]);
            s_tk[0][tid] = uL;
            s_tk[1][tid] = uR;
            int base = b * 48;
            out[base + 16 + k] = uL;
            out[base + 24 + k] = uR;
            out[base + 32 + k] = fc;
            out[base + 40 + k] = vf;
        }
        BARM();

        // ---- input layer ----
        float pre[4];
        {
            int n = tid;
            float wv[6];
            #pragma unroll
            for (int f = 0; f < 6; f++) wv[f] = w_in[f * Hn + n];
            float bi = b_in[n];
            #pragma unroll
            for (int t = 0; t < 4; t++) {
                float uL = s_tk[0][t], uR = s_tk[1][t];
                float df = uL - uR;
                float sg = (df > 0.f) ? 1.f : ((df < 0.f) ? -1.f : 0.f);
                float p = bi;
                p = fmaf(uL, wv[0], p);
                p = fmaf(uR, wv[1], p);
                p = fmaf(df, wv[2], p);
                p = fmaf(fabsf(df), wv[3], p);
                p = fmaf(0.5f * (uL + uR), wv[4], p);
                p = fmaf(sg, wv[5], p);
                pre[t] = p;
                s_ztd[tid * 4 + t] = dup2(p);
            }
        }
        BARM();
        ln_stats_m((const float*)s_ztd, 2, s_mu, s_rs, tid);
        {
            float lg = ln_in_g[tid], lb = ln_in_b[tid];
            float4 hv;
            hv.x = gelu_f((pre[0] - s_mu[0]) * s_rs[0] * lg + lb);
            hv.y = gelu_f((pre[1] - s_mu[1]) * s_rs[1] * lg + lb);
            hv.z = gelu_f((pre[2] - s_mu[2]) * s_rs[2] * lg + lb);
            hv.w = gelu_f((pre[3] - s_mu[3]) * s_rs[3] * lg + lb);
            *(float4*)(s_h + tid * 4) = hv;
        }
        BARM();

        const int ks = tid >> 7;   // split-K group 0..1
        const int cg = tid & 127;  // column group

        // ---- 3 residual blocks ----
        for (int i = 0; i < 3; i++) {
            ln_stats_m(s_h, 1, s_mu, s_rs, tid);
            {
                float g = rb_ln_g[i * Hn + tid], bb = rb_ln_b[i * Hn + tid];
                float4 hv = *(const float4*)(s_h + tid * 4);
                s_ztd[tid * 4 + 0] = dup2((hv.x - s_mu[0]) * s_rs[0] * g + bb);
                s_ztd[tid * 4 + 1] = dup2((hv.y - s_mu[1]) * s_rs[1] * g + bb);
                s_ztd[tid * 4 + 2] = dup2((hv.z - s_mu[2]) * s_rs[2] * g + bb);
                s_ztd[tid * 4 + 3] = dup2((hv.w - s_mu[3]) * s_rs[3] * g + bb);
            }
            BARM();

            // ===== GEMM1: cols 4cg..4cg+3, rows ks*16..+16 per 32-row tile =====
            {
                ull acc[4][2];
                #pragma unroll
                for (int t = 0; t < 4; t++) { acc[t][0] = 0ull; acc[t][1] = 0ull; }
                #pragma unroll
                for (int t8 = 0; t8 < 8; t8++) {
                    int jglob = i * 16 + t8;
                    mbar_wait(mbf[jglob % DEPTH], (uint32_t)((jglob / DEPTH) & 1));
                    const float* cur = ringf + (jglob % DEPTH) * TILE_FLOATS;
                    #pragma unroll
                    for (int kk = 0; kk < 16; kk++) {
                        int kl = ks * 16 + kk;
                        int kg = t8 * 32 + kl;
                        ull w01, w23, z0, z1, z2, z3;
                        lds128(w01, w23, (const ull*)(cur + kl * 512 + 4 * cg));
                        lds128(z0, z1, &s_ztd[kg * 4 + 0]);
                        lds128(z2, z3, &s_ztd[kg * 4 + 2]);
                        ffma2(acc[0][0], w01, z0); ffma2(acc[0][1], w23, z0);
                        ffma2(acc[1][0], w01, z1); ffma2(acc[1][1], w23, z1);
                        ffma2(acc[2][0], w01, z2); ffma2(acc[2][1], w23, z2);
                        ffma2(acc[3][0], w01, z3); ffma2(acc[3][1], w23, z3);
                    }
                    TILE_RELEASE(jglob);
                    TILE_ISSUE();
                }
                // s_rd overlays s_ztd: all ztd reads completed before the final
                // TILE_RELEASE's BARM above.
                if (ks == 1) {
                    #pragma unroll
                    for (int t = 0; t < 4; t++) {
                        s_rd[(t * 2 + 0) * 128 + cg] = acc[t][0];
                        s_rd[(t * 2 + 1) * 128 + cg] = acc[t][1];
                    }
                }
                float4 b1v = make_float4(0.f, 0.f, 0.f, 0.f);
                if (ks == 0) b1v = *(const float4*)(rb_b1 + i * 512 + 4 * cg);
                BARM();
                if (ks == 0) {
                    #pragma unroll
                    for (int t = 0; t < 4; t++) {
                        ull a0 = addf2(acc[t][0], s_rd[(t * 2 + 0) * 128 + cg]);
                        ull a1 = addf2(acc[t][1], s_rd[(t * 2 + 1) * 128 + cg]);
                        float2 u01 = unpk(a0), u23 = unpk(a1);
                        s_zzd[(4 * cg + 0) * 4 + t] = dup2(gelu_f(u01.x + b1v.x));
                        s_zzd[(4 * cg + 1) * 4 + t] = dup2(gelu_f(u01.y + b1v.y));
                        s_zzd[(4 * cg + 2) * 4 + t] = dup2(gelu_f(u23.x + b1v.z));
                        s_zzd[(4 * cg + 3) * 4 + t] = dup2(gelu_f(u23.y + b1v.w));
                    }
                }
                BARM();
            }

            // ===== GEMM2: cols 2cg..2cg+1, rows ks*32..+32 per 64-row tile =====
            {
                ull acc[4];
                #pragma unroll
                for (int t = 0; t < 4; t++) acc[t] = 0ull;
                #pragma unroll
                for (int t8 = 0; t8 < 8; t8++) {
                    int jglob = i * 16 + 8 + t8;
                    mbar_wait(mbf[jglob % DEPTH], (uint32_t)((jglob / DEPTH) & 1));
                    const float* cur = ringf + (jglob % DEPTH) * TILE_FLOATS;
                    #pragma unroll
                    for (int kk = 0; kk < 32; kk++) {
                        int kl = ks * 32 + kk;
                        int kg = t8 * 64 + kl;
                        ull w01 = *(const ull*)(cur + kl * 256 + 2 * cg);
                        ull z0, z1, z2, z3;
                        lds128(z0, z1, &s_zzd[kg * 4 + 0]);
                        lds128(z2, z3, &s_zzd[kg * 4 + 2]);
                        ffma2(acc[0], w01, z0);
                        ffma2(acc[1], w01, z1);
                        ffma2(acc[2], w01, z2);
                        ffma2(acc[3], w01, z3);
                    }
                    TILE_RELEASE(jglob);
                    TILE_ISSUE();
                }
                if (ks == 1) {
                    #pragma unroll
                    for (int t = 0; t < 4; t++)
                        s_rd[t * 128 + cg] = acc[t];
                }
                float2 b2v = make_float2(0.f, 0.f);
                if (ks == 0) b2v = *(const float2*)(rb_b2 + i * 256 + 2 * cg);
                BARM();
                if (ks == 0) {
                    float2 u[4];
                    #pragma unroll
                    for (int t = 0; t < 4; t++)
                        u[t] = unpk(addf2(acc[t], s_rd[t * 128 + cg]));
                    float4 h0 = *(const float4*)(s_h + (2 * cg + 0) * 4);
                    float4 h1 = *(const float4*)(s_h + (2 * cg + 1) * 4);
                    h0.x += u[0].x + b2v.x; h0.y += u[1].x + b2v.x;
                    h0.z += u[2].x + b2v.x; h0.w += u[3].x + b2v.x;
                    h1.x += u[0].y + b2v.y; h1.y += u[1].y + b2v.y;
                    h1.z += u[2].y + b2v.y; h1.w += u[3].y + b2v.y;
                    *(float4*)(s_h + (2 * cg + 0) * 4) = h0;
                    *(float4*)(s_h + (2 * cg + 1) * 4) = h1;
                }
                BARM();
            }
        }

        // ---- output head ----
        ln_stats_m(s_h, 1, s_mu, s_rs, tid);
        {
            float og = out_ln_g[tid], ob = out_ln_b[tid];
            float4 hv = *(const float4*)(s_h + tid * 4);
            float4 zv;
            zv.x = (hv.x - s_mu[0]) * s_rs[0] * og + ob;
            zv.y = (hv.y - s_mu[1]) * s_rs[1] * og + ob;
            zv.z = (hv.z - s_mu[2]) * s_rs[2] * og + ob;
            zv.w = (hv.w - s_mu[3]) * s_rs[3] * og + ob;
            *(float4*)(s_zp + tid * 4) = zv;
        }
        BARM();

        // a1 = gelu(z @ out_w1 + b1): col cg, rows ks*64..+64 per 128-row tile
        {
            float a[4] = {0.f, 0.f, 0.f, 0.f};
            #pragma unroll
            for (int t8 = 0; t8 < 2; t8++) {
                int jglob = 48 + t8;
                mbar_wait(mbf[jglob % DEPTH], (uint32_t)((jglob / DEPTH) & 1));
                const float* cur = ringf + (jglob % DEPTH) * TILE_FLOATS;
                #pragma unroll 8
                for (int kk = 0; kk < 64; kk++) {
                    int kl = ks * 64 + kk;
                    int kg = t8 * 128 + kl;
                    float w = cur[kl * 128 + cg];
                    float4 z = *(const float4*)(s_zp + kg * 4);
                    a[0] = fmaf(z.x, w, a[0]);
                    a[1] = fmaf(z.y, w, a[1]);
                    a[2] = fmaf(z.z, w, a[2]);
                    a[3] = fmaf(z.w, w, a[3]);
                }
                TILE_RELEASE(jglob);
            }
            // s_rdf overlays s_ztd (free during head; reduction barrier-separated)
            if (ks == 1) {
                #pragma unroll
                for (int t = 0; t < 4; t++)
                    s_rdf[t * 128 + cg] = a[t];
            }
            float bo = 0.f;
            if (ks == 0) bo = out_b1[cg];
            BARM();
            if (ks == 0) {
                #pragma unroll
                for (int t = 0; t < 4; t++)
                    a[t] += s_rdf[t * 128 + cg];
                *(float4*)(s_a1 + cg * 4) = make_float4(
                    gelu_f(a[0] + bo), gelu_f(a[1] + bo),
                    gelu_f(a[2] + bo), gelu_f(a[3] + bo));
            }
            BARM();
        }

        // speed = a1 @ out_w2 + out_b2: warps 0..7 -> (token, col)
        {
            int w = tid >> 5, lane = tid & 31;
            int t = w >> 1, cc = w & 1;
            float s = 0.f;
            s = fmaf(s_a1[(lane)      * 4 + t], out_w2[lane * 2 + cc],        s);
            s = fmaf(s_a1[(lane + 32) * 4 + t], out_w2[(lane + 32) * 2 + cc], s);
            s = fmaf(s_a1[(lane + 64) * 4 + t], out_w2[(lane + 64) * 2 + cc], s);
            s = fmaf(s_a1[(lane + 96) * 4 + t], out_w2[(lane + 96) * 2 + cc], s);
            #pragma unroll
            for (int o = 16; o; o >>= 1) s += __shfl_xor_sync(0xffffffffu, s, o);
            if (lane == 0)
                out[b * 48 + cc * 8 + (kbase + t)] = s + out_b2[cc];
        }
    }

    CLUSTER_SYNC_();
}

extern "C" void kernel_launch(void* const* d_in, const int* in_sizes, int n_in,
                              void* d_out, int out_size) {
    const float* x        = (const float*)d_in[0];
    const float* w_in     = (const float*)d_in[1];
    const float* b_in     = (const float*)d_in[2];
    const float* ln_in_g  = (const float*)d_in[3];
    const float* ln_in_b  = (const float*)d_in[4];
    const float* rb_ln_g  = (const float*)d_in[5];
    const float* rb_ln_b  = (const float*)d_in[6];
    const float* rb_w1    = (const float*)d_in[7];
    const float* rb_b1    = (const float*)d_in[8];
    const float* rb_w2    = (const float*)d_in[9];
    const float* rb_b2    = (const float*)d_in[10];
    const float* out_ln_g = (const float*)d_in[11];
    const float* out_ln_b = (const float*)d_in[12];
    const float* out_w1   = (const float*)d_in[13];
    const float* out_b1   = (const float*)d_in[14];
    const float* out_w2   = (const float*)d_in[15];
    const float* out_b2   = (const float*)d_in[16];
    float* out = (float*)d_out;

    // ring(192KB) + s_h(4KB) + region B(8KB: ztd/rd) + region A(16KB: zzd/zp/a1) = 220KB
    const int smem_bytes = DEPTH * TILE_FLOATS * 4 + 4096 + 8192 + 16384;
    cudaFuncSetAttribute(fused_all, cudaFuncAttributeMaxDynamicSharedMemorySize, smem_bytes);

    fused_all<<<128, NT, smem_bytes>>>(x, w_in, b_in, ln_in_g, ln_in_b,
                                       rb_ln_g, rb_ln_b, rb_w1, rb_b1, rb_w2, rb_b2,
                                       out_ln_g, out_ln_b, out_w1, out_b1, out_w2, out_b2,
                                       out);
}

// round 16
// speedup vs baseline: 1.3474x; 1.0382x over previous
#include <cuda_runtime.h>
#include <math.h>
#include <stdint.h>

#define Xn 262144
#define Bn 64
#define Hn 256
#define THRF 1e-6f
#define NT 512
#define TILE_FLOATS 16384   // 64KB weight tile
#define NTILES 50           // 3*16 residual tiles + 2 head tiles
#define DEPTH 2
#define CLU 4

typedef unsigned long long ull;

// 2-party count handshake (zero-init; reset each run -> replay safe)
__device__ int g_part[Bn][2];
__device__ unsigned g_flag[Bn];

__device__ __forceinline__ float gelu_f(float v) {
    return 0.5f * v * (1.0f + erff(v * 0.70710678118654752f));
}
__device__ __forceinline__ void ffma2(ull& d, ull a, ull b) {
    asm("fma.rn.f32x2 %0, %1, %2, %0;" : "+l"(d) : "l"(a), "l"(b));
}
__device__ __forceinline__ ull addf2(ull a, ull b) {
    ull r; asm("add.rn.f32x2 %0, %1, %2;" : "=l"(r) : "l"(a), "l"(b)); return r;
}
__device__ __forceinline__ ull dup2(float v) {
    ull r; asm("mov.b64 %0, {%1, %1};" : "=l"(r) : "f"(v)); return r;
}
__device__ __forceinline__ float2 unpk(ull v) {
    float2 f; asm("mov.b64 {%0, %1}, %2;" : "=f"(f.x), "=f"(f.y) : "l"(v)); return f;
}
__device__ __forceinline__ uint32_t smem_u32(const void* p) {
    return (uint32_t)__cvta_generic_to_shared(p);
}
// 16-byte shared load as two ulls
__device__ __forceinline__ void lds128(ull& a, ull& b, const void* p) {
    uint32_t addr = smem_u32(p);
    asm volatile("ld.shared.v2.u64 {%0, %1}, [%2];" : "=l"(a), "=l"(b) : "r"(addr));
}

#define MBAR_INIT(addr, cnt) \
    asm volatile("mbarrier.init.shared.b64 [%0], %1;" :: "r"(addr), "r"(cnt) : "memory")
#define MBAR_EXPECT_TX(addr, bytes) \
    asm volatile("mbarrier.arrive.expect_tx.shared.b64 _, [%0], %1;" :: "r"(addr), "r"(bytes) : "memory")
#define MBAR_ARRIVE_CLUSTER(addr, rk) \
    asm volatile("{\n\t.reg .b32 ra%=;\n\tmapa.shared::cluster.u32 ra%=, %0, %1;\n\t" \
                 "mbarrier.arrive.shared::cluster.b64 _, [ra%=];\n\t}" \
                 :: "r"(addr), "r"(rk) : "memory")

__device__ __forceinline__ void mbar_wait(uint32_t addr, uint32_t parity) {
    asm volatile(
        "{\n\t.reg .pred P%=;\n\t"
        "WL%=:\n\t"
        "mbarrier.try_wait.parity.acquire.cta.shared::cta.b64 P%=, [%0], %1, 0x989680;\n\t"
        "@!P%= bra WL%=;\n\t}"
        :: "r"(addr), "r"(parity) : "memory");
}
__device__ __forceinline__ void bulk_mcast(uint32_t dst, const float* src, uint32_t mbar) {
    asm volatile(
        "cp.async.bulk.shared::cluster.global.mbarrier::complete_tx::bytes.multicast::cluster"
        " [%0], [%1], %2, [%3], %4;"
        :: "r"(dst), "l"(src), "r"(16384u), "r"(mbar), "h"((unsigned short)0xF)
        : "memory");
}
#define CLUSTER_SYNC_() do { \
    asm volatile("barrier.cluster.arrive.aligned;" ::: "memory"); \
    asm volatile("barrier.cluster.wait.aligned;" ::: "memory"); \
} while (0)

#define BARM() asm volatile("bar.sync 1, 256;" ::: "memory")
#define BARS() asm volatile("bar.sync 2, 256;" ::: "memory")

// LN stats over token-interleaved buffer: (col c, token t) at buf[c*4+t]
__device__ __forceinline__ void ln_stats_m(const float* buf,
                                           float* s_mu, float* s_rs, int tid) {
    int w = tid >> 5, lane = tid & 31;
    if (w < 4) {
        float s1 = 0.f, s2 = 0.f;
        #pragma unroll
        for (int j = 0; j < 8; j++) {
            float v = buf[(lane + 32 * j) * 4 + w];
            s1 += v;
            s2 = fmaf(v, v, s2);
        }
        #pragma unroll
        for (int o = 16; o; o >>= 1) {
            s1 += __shfl_xor_sync(0xffffffffu, s1, o);
            s2 += __shfl_xor_sync(0xffffffffu, s2, o);
        }
        if (lane == 0) {
            float mu = s1 * (1.f / 256.f);
            float var = fmaxf(s2 * (1.f / 256.f) - mu * mu, 0.f);
            s_mu[w] = mu;
            s_rs[w] = rsqrtf(var + 1e-5f);
        }
    }
    BARM();
}

__global__ void __launch_bounds__(NT, 1) __cluster_dims__(CLU, 1, 1) fused_all(
    const float* __restrict__ x,
    const float* __restrict__ w_in,  const float* __restrict__ b_in,
    const float* __restrict__ ln_in_g, const float* __restrict__ ln_in_b,
    const float* __restrict__ rb_ln_g, const float* __restrict__ rb_ln_b,
    const float* __restrict__ rb_w1,  const float* __restrict__ rb_b1,
    const float* __restrict__ rb_w2,  const float* __restrict__ rb_b2,
    const float* __restrict__ out_ln_g, const float* __restrict__ out_ln_b,
    const float* __restrict__ out_w1, const float* __restrict__ out_b1,
    const float* __restrict__ out_w2, const float* __restrict__ out_b2,
    float* __restrict__ out)
{
    const int tid  = threadIdx.x;
    const uint32_t rank = (uint32_t)(blockIdx.x & 3);
    const int b     = blockIdx.x >> 1;
    const int half  = blockIdx.x & 1;
    const int kbase = half * 4;
    const float* d  = x + (size_t)b * 2 * Xn;
    const float* cr = d + Xn;

    extern __shared__ float smem[];
    float* ringf = smem;
    float* s_h   = smem + DEPTH * TILE_FLOATS;   // 1024 f [col*4+t]
    float* s_zp  = s_h + 1024;                   // 1024 f plain z  [k*4+t]
    float* s_zzp = s_zp + 1024;                  // 2048 f plain zz [k*4+t]
    float* s_a1  = s_zzp + 2048;                 // 1024 f a1 [col*4+t]
    ull*   s_rd  = (ull*)(s_a1 + 1024);          // 1536 ull scratch (12KB)
    float* s_rdf = (float*)s_rd;

    __shared__ uint64_t mb_full[DEPTH], mb_empty[DEPTH];
    __shared__ const float* s_tiles[NTILES];
    __shared__ float s_mu[4], s_rs[4];
    __shared__ float s_tk[2][4];
    __shared__ unsigned s_wm[8], s_vm[8];
    __shared__ int s_idx[8], s_non[8];
    __shared__ int s_nd, s_nn, s_done;
    __shared__ int cw[8];

    const uint32_t slot_base = smem_u32(smem);
    uint32_t mbf[DEPTH], mbe[DEPTH];
    #pragma unroll
    for (int s = 0; s < DEPTH; s++) {
        mbf[s] = smem_u32(&mb_full[s]);
        mbe[s] = smem_u32(&mb_empty[s]);
    }

    if (tid == 0) {
        #pragma unroll
        for (int s = 0; s < DEPTH; s++) {
            MBAR_INIT(mbf[s], 1u);
            MBAR_INIT(mbe[s], 4u);
        }
        s_nd = 0; s_nn = 0; s_done = 0;
    }
    if (tid < NTILES) {
        int j = tid;
        const float* p;
        if (j < 48) {
            int ph = j >> 4, w = j & 15;
            p = (w < 8) ? rb_w1 + (size_t)ph * 131072 + (size_t)w * TILE_FLOATS
                        : rb_w2 + (size_t)ph * 131072 + (size_t)(w - 8) * TILE_FLOATS;
        } else {
            p = out_w1 + (size_t)(j - 48) * TILE_FLOATS;
        }
        s_tiles[j] = p;
    }
    __syncthreads();
    CLUSTER_SYNC_();

    int gt = 0;
    #define TILE_ISSUE()                                                          \
        if (gt < NTILES) {                                                        \
            if (tid == 0) {                                                       \
                int ss = gt % DEPTH;                                              \
                mbar_wait(mbe[ss], (uint32_t)(((gt / DEPTH) & 1) ^ 1));           \
                MBAR_EXPECT_TX(mbf[ss], 65536u);                                  \
                bulk_mcast(slot_base + (uint32_t)ss * 65536u + rank * 16384u,     \
                           s_tiles[gt] + rank * 4096, mbf[ss]);                   \
            }                                                                     \
            gt++;                                                                 \
        }
    #define TILE_RELEASE(jglob)                                                   \
        BARM();                                                                   \
        if (tid == 0) {                                                           \
            int ss = (jglob) % DEPTH;                                             \
            MBAR_ARRIVE_CLUSTER(mbe[ss], 0u);                                     \
            MBAR_ARRIVE_CLUSTER(mbe[ss], 1u);                                     \
            MBAR_ARRIVE_CLUSTER(mbe[ss], 2u);                                     \
            MBAR_ARRIVE_CLUSTER(mbe[ss], 3u);                                     \
        }

    // prime both ring slots (land during scan/front-find)
    TILE_ISSUE();
    TILE_ISSUE();

    if (tid >= 256) {
        // ================= SCAN WARPS (8-15): count this half-row =================
        int stid = tid - 256;
        const float4* d4 = (const float4*)d;
        const int start4 = (half * (Xn / 2)) >> 2;
        const int iend   = half ? (Xn - 1) : (Xn / 2);
        int cnt = 0;
        #pragma unroll 4
        for (int it = 0; it < (Xn / 2) / (256 * 4); it++) {
            int i4 = start4 + stid + it * 256;
            float4 v = __ldcs(&d4[i4]);
            int j0 = i4 << 2;
            bool cross = (j0 + 3) < iend;
            float nxt = __shfl_down_sync(0xffffffffu, v.x, 1);
            if ((stid & 31) == 31)
                nxt = cross ? __ldcs(&d[j0 + 4]) : 0.f;
            cnt += (fabsf(v.x - v.y) > THRF);
            cnt += (fabsf(v.y - v.z) > THRF);
            cnt += (fabsf(v.z - v.w) > THRF);
            cnt += (cross && (fabsf(v.w - nxt) > THRF));
        }
        #pragma unroll
        for (int o = 16; o; o >>= 1) cnt += __shfl_xor_sync(0xffffffffu, cnt, o);
        if ((stid & 31) == 0) cw[stid >> 5] = cnt;
        BARS();
        if (stid == 0) {
            int s = 0;
            #pragma unroll
            for (int w = 0; w < 8; w++) s += cw[w];
            g_part[b][half] = s;
            __threadfence();
            unsigned old = atomicAdd(&g_flag[b], 1u);
            if (old == 1u) {
                out[Bn * 48 + b] = (float)(s + g_part[b][half ^ 1]);
                g_flag[b] = 0u;
            }
        }
    } else {
        // ================= MLP WARPS (0-7): front-find + network =================

        // ---- find first 8 discontinuities (ordered), 256-wide chunks ----
        for (int base = 0; base < Xn - 1; base += 256) {
            int i = base + tid;
            bool valid = (i < Xn - 1);
            bool disc = valid && (fabsf(d[i] - d[i + 1]) > THRF);
            unsigned m  = __ballot_sync(0xffffffffu, disc);
            unsigned vm = __ballot_sync(0xffffffffu, valid);
            if ((tid & 31) == 0) { s_wm[tid >> 5] = m; s_vm[tid >> 5] = vm; }
            BARM();
            if (tid == 0) {
                for (int w = 0; w < 8 && s_nd < 8; w++) {
                    unsigned mm = s_wm[w], vv = s_vm[w];
                    int ib = base + w * 32;
                    while (vv) {
                        int lane = __ffs(vv) - 1;
                        vv &= vv - 1;
                        int idx = ib + lane;
                        if ((mm >> lane) & 1u) {
                            if (s_nd < 8) {
                                s_idx[s_nd++] = idx;
                                if (s_nd >= 8) break;
                            }
                        } else {
                            if (s_nn < 8) s_non[s_nn++] = idx;
                        }
                    }
                }
                if (s_nd >= 8) s_done = 1;
            }
            BARM();
            if (s_done) break;
        }
        if (tid < 4) {
            int k = kbase + tid;
            int nd = s_nd;
            int i; float vf;
            if (k < nd) { i = s_idx[k]; vf = 1.0f; }
            else        { i = s_non[k - nd]; vf = 0.0f; }
            float uL = d[i], uR = d[i + 1];
            float fc = 0.5f * (cr[i] + cr[i + 1]);
            s_tk[0][tid] = uL;
            s_tk[1][tid] = uR;
            int base = b * 48;
            out[base + 16 + k] = uL;
            out[base + 24 + k] = uR;
            out[base + 32 + k] = fc;
            out[base + 40 + k] = vf;
        }
        BARM();

        // ---- input layer: pre (plain) -> LN -> gelu -> s_h ----
        float pre[4];
        {
            int n = tid;
            float wv[6];
            #pragma unroll
            for (int f = 0; f < 6; f++) wv[f] = w_in[f * Hn + n];
            float bi = b_in[n];
            #pragma unroll
            for (int t = 0; t < 4; t++) {
                float uL = s_tk[0][t], uR = s_tk[1][t];
                float df = uL - uR;
                float sg = (df > 0.f) ? 1.f : ((df < 0.f) ? -1.f : 0.f);
                float p = bi;
                p = fmaf(uL, wv[0], p);
                p = fmaf(uR, wv[1], p);
                p = fmaf(df, wv[2], p);
                p = fmaf(fabsf(df), wv[3], p);
                p = fmaf(0.5f * (uL + uR), wv[4], p);
                p = fmaf(sg, wv[5], p);
                pre[t] = p;
            }
            *(float4*)(s_zp + n * 4) = make_float4(pre[0], pre[1], pre[2], pre[3]);
        }
        BARM();
        ln_stats_m(s_zp, s_mu, s_rs, tid);
        {
            float lg = ln_in_g[tid], lb = ln_in_b[tid];
            float4 hv;
            hv.x = gelu_f((pre[0] - s_mu[0]) * s_rs[0] * lg + lb);
            hv.y = gelu_f((pre[1] - s_mu[1]) * s_rs[1] * lg + lb);
            hv.z = gelu_f((pre[2] - s_mu[2]) * s_rs[2] * lg + lb);
            hv.w = gelu_f((pre[3] - s_mu[3]) * s_rs[3] * lg + lb);
            *(float4*)(s_h + tid * 4) = hv;
        }
        BARM();

        // ---- 3 residual blocks ----
        for (int i = 0; i < 3; i++) {
            ln_stats_m(s_h, s_mu, s_rs, tid);
            {
                float g = rb_ln_g[i * Hn + tid], bb = rb_ln_b[i * Hn + tid];
                float4 hv = *(const float4*)(s_h + tid * 4);
                float4 zv;
                zv.x = (hv.x - s_mu[0]) * s_rs[0] * g + bb;
                zv.y = (hv.y - s_mu[1]) * s_rs[1] * g + bb;
                zv.z = (hv.z - s_mu[2]) * s_rs[2] * g + bb;
                zv.w = (hv.w - s_mu[3]) * s_rs[3] * g + bb;
                *(float4*)(s_zp + tid * 4) = zv;
            }
            BARM();

            // ===== GEMM1: thread (ks=tid>>7, cg=tid&127) -> cols 4cg..4cg+3,
            //       token-pair FFMA2; acc[c][p] = (t0,t1)/(t2,t3) sums =====
            {
                const int ks = tid >> 7, cg = tid & 127;
                ull acc[4][2];
                #pragma unroll
                for (int c = 0; c < 4; c++) { acc[c][0] = 0ull; acc[c][1] = 0ull; }
                #pragma unroll
                for (int t8 = 0; t8 < 8; t8++) {
                    int jglob = i * 16 + t8;
                    mbar_wait(mbf[jglob % DEPTH], (uint32_t)((jglob / DEPTH) & 1));
                    const float* cur = ringf + (jglob % DEPTH) * TILE_FLOATS;
                    #pragma unroll
                    for (int kk = 0; kk < 16; kk++) {
                        int kl = ks * 16 + kk;
                        int kg = t8 * 32 + kl;
                        ull w01, w23, z01, z23;
                        lds128(w01, w23, cur + kl * 512 + 4 * cg);
                        lds128(z01, z23, s_zp + kg * 4);
                        float2 wa = unpk(w01), wb = unpk(w23);
                        ull w0 = dup2(wa.x), w1 = dup2(wa.y);
                        ull w2 = dup2(wb.x), w3 = dup2(wb.y);
                        ffma2(acc[0][0], w0, z01); ffma2(acc[0][1], w0, z23);
                        ffma2(acc[1][0], w1, z01); ffma2(acc[1][1], w1, z23);
                        ffma2(acc[2][0], w2, z01); ffma2(acc[2][1], w2, z23);
                        ffma2(acc[3][0], w3, z01); ffma2(acc[3][1], w3, z23);
                    }
                    TILE_RELEASE(jglob);
                    TILE_ISSUE();
                }
                if (ks == 1) {
                    #pragma unroll
                    for (int c = 0; c < 4; c++) {
                        s_rd[(c * 2 + 0) * 128 + cg] = acc[c][0];
                        s_rd[(c * 2 + 1) * 128 + cg] = acc[c][1];
                    }
                }
                float4 b1v = make_float4(0.f, 0.f, 0.f, 0.f);
                if (ks == 0) b1v = *(const float4*)(rb_b1 + i * 512 + 4 * cg);
                BARM();
                if (ks == 0) {
                    const float* bp = &b1v.x;
                    #pragma unroll
                    for (int c = 0; c < 4; c++) {
                        ull a01 = addf2(acc[c][0], s_rd[(c * 2 + 0) * 128 + cg]);
                        ull a23 = addf2(acc[c][1], s_rd[(c * 2 + 1) * 128 + cg]);
                        float2 u01 = unpk(a01), u23 = unpk(a23);
                        float bb = bp[c];
                        *(float4*)(s_zzp + (4 * cg + c) * 4) = make_float4(
                            gelu_f(u01.x + bb), gelu_f(u01.y + bb),
                            gelu_f(u23.x + bb), gelu_f(u23.y + bb));
                    }
                }
                BARM();
            }

            // ===== GEMM2: thread (ks4=tid>>6, cg6=tid&63) -> cols 4cg6..4cg6+3,
            //       4-way split-K over 64-row tiles, token-pair FFMA2 =====
            {
                const int ks4 = tid >> 6, cg6 = tid & 63;
                ull acc[4][2];
                #pragma unroll
                for (int c = 0; c < 4; c++) { acc[c][0] = 0ull; acc[c][1] = 0ull; }
                #pragma unroll
                for (int t8 = 0; t8 < 8; t8++) {
                    int jglob = i * 16 + 8 + t8;
                    mbar_wait(mbf[jglob % DEPTH], (uint32_t)((jglob / DEPTH) & 1));
                    const float* cur = ringf + (jglob % DEPTH) * TILE_FLOATS;
                    #pragma unroll
                    for (int kk = 0; kk < 16; kk++) {
                        int kl = ks4 * 16 + kk;
                        int kg = t8 * 64 + kl;
                        ull w01, w23, z01, z23;
                        lds128(w01, w23, cur + kl * 256 + 4 * cg6);
                        lds128(z01, z23, s_zzp + kg * 4);
                        float2 wa = unpk(w01), wb = unpk(w23);
                        ull w0 = dup2(wa.x), w1 = dup2(wa.y);
                        ull w2 = dup2(wb.x), w3 = dup2(wb.y);
                        ffma2(acc[0][0], w0, z01); ffma2(acc[0][1], w0, z23);
                        ffma2(acc[1][0], w1, z01); ffma2(acc[1][1], w1, z23);
                        ffma2(acc[2][0], w2, z01); ffma2(acc[2][1], w2, z23);
                        ffma2(acc[3][0], w3, z01); ffma2(acc[3][1], w3, z23);
                    }
                    TILE_RELEASE(jglob);
                    TILE_ISSUE();
                }
                if (ks4 > 0) {
                    int km = ks4 - 1;
                    #pragma unroll
                    for (int c = 0; c < 4; c++) {
                        s_rd[(km * 8 + c * 2 + 0) * 64 + cg6] = acc[c][0];
                        s_rd[(km * 8 + c * 2 + 1) * 64 + cg6] = acc[c][1];
                    }
                }
                float4 b2v = make_float4(0.f, 0.f, 0.f, 0.f);
                if (ks4 == 0) b2v = *(const float4*)(rb_b2 + i * 256 + 4 * cg6);
                BARM();
                if (ks4 == 0) {
                    const float* bp = &b2v.x;
                    #pragma unroll
                    for (int c = 0; c < 4; c++) {
                        ull a01 = acc[c][0], a23 = acc[c][1];
                        #pragma unroll
                        for (int km = 0; km < 3; km++) {
                            a01 = addf2(a01, s_rd[(km * 8 + c * 2 + 0) * 64 + cg6]);
                            a23 = addf2(a23, s_rd[(km * 8 + c * 2 + 1) * 64 + cg6]);
                        }
                        float2 u01 = unpk(a01), u23 = unpk(a23);
                        int col = 4 * cg6 + c;
                        float bb = bp[c];
                        float4 hv = *(const float4*)(s_h + col * 4);
                        hv.x += u01.x + bb;
                        hv.y += u01.y + bb;
                        hv.z += u23.x + bb;
                        hv.w += u23.y + bb;
                        *(float4*)(s_h + col * 4) = hv;
                    }
                }
                BARM();
            }
        }

        // ---- output head ----
        ln_stats_m(s_h, s_mu, s_rs, tid);
        {
            float og = out_ln_g[tid], ob = out_ln_b[tid];
            float4 hv = *(const float4*)(s_h + tid * 4);
            float4 zv;
            zv.x = (hv.x - s_mu[0]) * s_rs[0] * og + ob;
            zv.y = (hv.y - s_mu[1]) * s_rs[1] * og + ob;
            zv.z = (hv.z - s_mu[2]) * s_rs[2] * og + ob;
            zv.w = (hv.w - s_mu[3]) * s_rs[3] * og + ob;
            *(float4*)(s_zp + tid * 4) = zv;
        }
        BARM();

        // a1 = gelu(z @ out_w1 + b1): col cg, rows ks*64..+64 per 128-row tile
        {
            const int ks = tid >> 7, cg = tid & 127;
            float a[4] = {0.f, 0.f, 0.f, 0.f};
            #pragma unroll
            for (int t8 = 0; t8 < 2; t8++) {
                int jglob = 48 + t8;
                mbar_wait(mbf[jglob % DEPTH], (uint32_t)((jglob / DEPTH) & 1));
                const float* cur = ringf + (jglob % DEPTH) * TILE_FLOATS;
                #pragma unroll 8
                for (int kk = 0; kk < 64; kk++) {
                    int kl = ks * 64 + kk;
                    int kg = t8 * 128 + kl;
                    float w = cur[kl * 128 + cg];
                    float4 z = *(const float4*)(s_zp + kg * 4);
                    a[0] = fmaf(z.x, w, a[0]);
                    a[1] = fmaf(z.y, w, a[1]);
                    a[2] = fmaf(z.z, w, a[2]);
                    a[3] = fmaf(z.w, w, a[3]);
                }
                TILE_RELEASE(jglob);
            }
            if (ks == 1) {
                #pragma unroll
                for (int t = 0; t < 4; t++)
                    s_rdf[t * 128 + cg] = a[t];
            }
            float bo = 0.f;
            if (ks == 0) bo = out_b1[cg];
            BARM();
            if (ks == 0) {
                #pragma unroll
                for (int t = 0; t < 4; t++)
                    a[t] += s_rdf[t * 128 + cg];
                *(float4*)(s_a1 + cg * 4) = make_float4(
                    gelu_f(a[0] + bo), gelu_f(a[1] + bo),
                    gelu_f(a[2] + bo), gelu_f(a[3] + bo));
            }
            BARM();
        }

        // speed = a1 @ out_w2 + out_b2: warps 0..7 -> (token, col)
        {
            int w = tid >> 5, lane = tid & 31;
            int t = w >> 1, cc = w & 1;
            float s = 0.f;
            s = fmaf(s_a1[(lane)      * 4 + t], out_w2[lane * 2 + cc],        s);
            s = fmaf(s_a1[(lane + 32) * 4 + t], out_w2[(lane + 32) * 2 + cc], s);
            s = fmaf(s_a1[(lane + 64) * 4 + t], out_w2[(lane + 64) * 2 + cc], s);
            s = fmaf(s_a1[(lane + 96) * 4 + t], out_w2[(lane + 96) * 2 + cc], s);
            #pragma unroll
            for (int o = 16; o; o >>= 1) s += __shfl_xor_sync(0xffffffffu, s, o);
            if (lane == 0)
                out[b * 48 + cc * 8 + (kbase + t)] = s + out_b2[cc];
        }
    }

    CLUSTER_SYNC_();
}

extern "C" void kernel_launch(void* const* d_in, const int* in_sizes, int n_in,
                              void* d_out, int out_size) {
    const float* x        = (const float*)d_in[0];
    const float* w_in     = (const float*)d_in[1];
    const float* b_in     = (const float*)d_in[2];
    const float* ln_in_g  = (const float*)d_in[3];
    const float* ln_in_b  = (const float*)d_in[4];
    const float* rb_ln_g  = (const float*)d_in[5];
    const float* rb_ln_b  = (const float*)d_in[6];
    const float* rb_w1    = (const float*)d_in[7];
    const float* rb_b1    = (const float*)d_in[8];
    const float* rb_w2    = (const float*)d_in[9];
    const float* rb_b2    = (const float*)d_in[10];
    const float* out_ln_g = (const float*)d_in[11];
    const float* out_ln_b = (const float*)d_in[12];
    const float* out_w1   = (const float*)d_in[13];
    const float* out_b1   = (const float*)d_in[14];
    const float* out_w2   = (const float*)d_in[15];
    const float* out_b2   = (const float*)d_in[16];
    float* out = (float*)d_out;

    // ring(128KB) + s_h(4KB) + zp(4KB) + zzp(8KB) + a1(4KB) + rd(12KB) = 160KB
    const int smem_bytes = DEPTH * TILE_FLOATS * 4 + 4096 + 4096 + 8192 + 4096 + 12288;
    cudaFuncSetAttribute(fused_all, cudaFuncAttributeMaxDynamicSharedMemorySize, smem_bytes);

    fused_all<<<128, NT, smem_bytes>>>(x, w_in, b_in, ln_in_g, ln_in_b,
                                       rb_ln_g, rb_ln_b, rb_w1, rb_b1, rb_w2, rb_b2,
                                       out_ln_g, out_ln_b, out_w1, out_b1, out_w2, out_b2,
                                       out);
}

// round 17
// speedup vs baseline: 1.6052x; 1.1914x over previous
#include <cuda_runtime.h>
#include <math.h>
#include <stdint.h>

#define Xn 262144
#define Bn 64
#define Hn 256
#define THRF 1e-6f
#define NT 512
#define TILE_FLOATS 16384   // 64KB weight tile
#define NTILES 50           // 3*16 residual tiles + 2 head tiles
#define DEPTH 2
#define CLU 4

typedef unsigned long long ull;

// 2-party count handshake (zero-init; reset each run -> replay safe)
__device__ int g_part[Bn][2];
__device__ unsigned g_flag[Bn];

__device__ __forceinline__ float gelu_f(float v) {
    return 0.5f * v * (1.0f + erff(v * 0.70710678118654752f));
}
__device__ __forceinline__ void ffma2(ull& d, ull a, ull b) {
    asm("fma.rn.f32x2 %0, %1, %2, %0;" : "+l"(d) : "l"(a), "l"(b));
}
__device__ __forceinline__ ull addf2(ull a, ull b) {
    ull r; asm("add.rn.f32x2 %0, %1, %2;" : "=l"(r) : "l"(a), "l"(b)); return r;
}
__device__ __forceinline__ ull dup2(float v) {
    ull r; asm("mov.b64 %0, {%1, %1};" : "=l"(r) : "f"(v)); return r;
}
__device__ __forceinline__ float2 unpk(ull v) {
    float2 f; asm("mov.b64 {%0, %1}, %2;" : "=f"(f.x), "=f"(f.y) : "l"(v)); return f;
}
__device__ __forceinline__ uint32_t smem_u32(const void* p) {
    return (uint32_t)__cvta_generic_to_shared(p);
}
// 16-byte shared load as two ulls
__device__ __forceinline__ void lds128(ull& a, ull& b, const void* p) {
    uint32_t addr = smem_u32(p);
    asm volatile("ld.shared.v2.u64 {%0, %1}, [%2];" : "=l"(a), "=l"(b) : "r"(addr));
}

#define MBAR_INIT(addr, cnt) \
    asm volatile("mbarrier.init.shared.b64 [%0], %1;" :: "r"(addr), "r"(cnt) : "memory")
#define MBAR_EXPECT_TX(addr, bytes) \
    asm volatile("mbarrier.arrive.expect_tx.shared.b64 _, [%0], %1;" :: "r"(addr), "r"(bytes) : "memory")
#define MBAR_ARRIVE_CLUSTER(addr, rk) \
    asm volatile("{\n\t.reg .b32 ra%=;\n\tmapa.shared::cluster.u32 ra%=, %0, %1;\n\t" \
                 "mbarrier.arrive.shared::cluster.b64 _, [ra%=];\n\t}" \
                 :: "r"(addr), "r"(rk) : "memory")

__device__ __forceinline__ void mbar_wait(uint32_t addr, uint32_t parity) {
    asm volatile(
        "{\n\t.reg .pred P%=;\n\t"
        "WL%=:\n\t"
        "mbarrier.try_wait.parity.acquire.cta.shared::cta.b64 P%=, [%0], %1, 0x989680;\n\t"
        "@!P%= bra WL%=;\n\t}"
        :: "r"(addr), "r"(parity) : "memory");
}
__device__ __forceinline__ void bulk_mcast(uint32_t dst, const float* src, uint32_t mbar) {
    asm volatile(
        "cp.async.bulk.shared::cluster.global.mbarrier::complete_tx::bytes.multicast::cluster"
        " [%0], [%1], %2, [%3], %4;"
        :: "r"(dst), "l"(src), "r"(16384u), "r"(mbar), "h"((unsigned short)0xF)
        : "memory");
}
#define CLUSTER_SYNC_() do { \
    asm volatile("barrier.cluster.arrive.aligned;" ::: "memory"); \
    asm volatile("barrier.cluster.wait.aligned;" ::: "memory"); \
} while (0)

#define BARM() asm volatile("bar.sync 1, 256;" ::: "memory")
#define BARS() asm volatile("bar.sync 2, 256;" ::: "memory")

// LN stats over token-interleaved buffer: (col c, token t) at buf[(c*4+t)*stride]
__device__ __forceinline__ void ln_stats_m(const float* buf, int stride,
                                           float* s_mu, float* s_rs, int tid) {
    int w = tid >> 5, lane = tid & 31;
    if (w < 4) {
        float s1 = 0.f, s2 = 0.f;
        #pragma unroll
        for (int j = 0; j < 8; j++) {
            float v = buf[((lane + 32 * j) * 4 + w) * stride];
            s1 += v;
            s2 = fmaf(v, v, s2);
        }
        #pragma unroll
        for (int o = 16; o; o >>= 1) {
            s1 += __shfl_xor_sync(0xffffffffu, s1, o);
            s2 += __shfl_xor_sync(0xffffffffu, s2, o);
        }
        if (lane == 0) {
            float mu = s1 * (1.f / 256.f);
            float var = fmaxf(s2 * (1.f / 256.f) - mu * mu, 0.f);
            s_mu[w] = mu;
            s_rs[w] = rsqrtf(var + 1e-5f);
        }
    }
    BARM();
}

__global__ void __launch_bounds__(NT, 1) __cluster_dims__(CLU, 1, 1) fused_all(
    const float* __restrict__ x,
    const float* __restrict__ w_in,  const float* __restrict__ b_in,
    const float* __restrict__ ln_in_g, const float* __restrict__ ln_in_b,
    const float* __restrict__ rb_ln_g, const float* __restrict__ rb_ln_b,
    const float* __restrict__ rb_w1,  const float* __restrict__ rb_b1,
    const float* __restrict__ rb_w2,  const float* __restrict__ rb_b2,
    const float* __restrict__ out_ln_g, const float* __restrict__ out_ln_b,
    const float* __restrict__ out_w1, const float* __restrict__ out_b1,
    const float* __restrict__ out_w2, const float* __restrict__ out_b2,
    float* __restrict__ out)
{
    const int tid  = threadIdx.x;
    const uint32_t rank = (uint32_t)(blockIdx.x & 3);
    const int b     = blockIdx.x >> 1;
    const int half  = blockIdx.x & 1;
    const int kbase = half * 4;
    const float* d  = x + (size_t)b * 2 * Xn;
    const float* cr = d + Xn;

    extern __shared__ float smem[];
    float* ringf = smem;
    float* s_h   = smem + DEPTH * TILE_FLOATS;           // 1024 f [col*4+t]
    ull*   s_ztd = (ull*)(s_h + 1024);                   // 1024 ull dup z [k*4+t]
    ull*   s_zzd = (ull*)(s_h + 1024 + 2048);            // 2048 ull dup zz [k*4+t]
    float* s_zp  = s_h + 1024 + 2048 + 4096;             // 1024 f plain z [k*4+t]
    float* s_a1  = s_zp + 1024;                          // 1024 f a1 [col*4+t]
    ull*   s_rd  = (ull*)(s_a1 + 1024);                  // 1536 ull scratch (12KB)
    float* s_rdf = (float*)s_rd;

    __shared__ uint64_t mb_full[DEPTH], mb_empty[DEPTH];
    __shared__ const float* s_tiles[NTILES];
    __shared__ float s_mu[4], s_rs[4];
    __shared__ float s_tk[2][4];
    __shared__ unsigned s_wm[8], s_vm[8];
    __shared__ int s_idx[8], s_non[8];
    __shared__ int s_nd, s_nn, s_done;
    __shared__ int cw[8];

    const uint32_t slot_base = smem_u32(smem);
    uint32_t mbf[DEPTH], mbe[DEPTH];
    #pragma unroll
    for (int s = 0; s < DEPTH; s++) {
        mbf[s] = smem_u32(&mb_full[s]);
        mbe[s] = smem_u32(&mb_empty[s]);
    }

    if (tid == 0) {
        #pragma unroll
        for (int s = 0; s < DEPTH; s++) {
            MBAR_INIT(mbf[s], 1u);
            MBAR_INIT(mbe[s], 4u);
        }
        s_nd = 0; s_nn = 0; s_done = 0;
    }
    if (tid < NTILES) {
        int j = tid;
        const float* p;
        if (j < 48) {
            int ph = j >> 4, w = j & 15;
            p = (w < 8) ? rb_w1 + (size_t)ph * 131072 + (size_t)w * TILE_FLOATS
                        : rb_w2 + (size_t)ph * 131072 + (size_t)(w - 8) * TILE_FLOATS;
        } else {
            p = out_w1 + (size_t)(j - 48) * TILE_FLOATS;
        }
        s_tiles[j] = p;
    }
    __syncthreads();
    CLUSTER_SYNC_();

    int gt = 0;
    #define TILE_ISSUE()                                                          \
        if (gt < NTILES) {                                                        \
            if (tid == 0) {                                                       \
                int ss = gt % DEPTH;                                              \
                mbar_wait(mbe[ss], (uint32_t)(((gt / DEPTH) & 1) ^ 1));           \
                MBAR_EXPECT_TX(mbf[ss], 65536u);                                  \
                bulk_mcast(slot_base + (uint32_t)ss * 65536u + rank * 16384u,     \
                           s_tiles[gt] + rank * 4096, mbf[ss]);                   \
            }                                                                     \
            gt++;                                                                 \
        }
    #define TILE_RELEASE(jglob)                                                   \
        BARM();                                                                   \
        if (tid == 0) {                                                           \
            int ss = (jglob) % DEPTH;                                             \
            MBAR_ARRIVE_CLUSTER(mbe[ss], 0u);                                     \
            MBAR_ARRIVE_CLUSTER(mbe[ss], 1u);                                     \
            MBAR_ARRIVE_CLUSTER(mbe[ss], 2u);                                     \
            MBAR_ARRIVE_CLUSTER(mbe[ss], 3u);                                     \
        }

    // prime both ring slots (land during scan/front-find)
    TILE_ISSUE();
    TILE_ISSUE();

    if (tid >= 256) {
        // ================= SCAN WARPS (8-15): count this half-row =================
        int stid = tid - 256;
        const float4* d4 = (const float4*)d;
        const int start4 = (half * (Xn / 2)) >> 2;
        const int iend   = half ? (Xn - 1) : (Xn / 2);
        int cnt = 0;
        #pragma unroll 4
        for (int it = 0; it < (Xn / 2) / (256 * 4); it++) {
            int i4 = start4 + stid + it * 256;
            float4 v = __ldcs(&d4[i4]);
            int j0 = i4 << 2;
            bool cross = (j0 + 3) < iend;
            float nxt = __shfl_down_sync(0xffffffffu, v.x, 1);
            if ((stid & 31) == 31)
                nxt = cross ? __ldcs(&d[j0 + 4]) : 0.f;
            cnt += (fabsf(v.x - v.y) > THRF);
            cnt += (fabsf(v.y - v.z) > THRF);
            cnt += (fabsf(v.z - v.w) > THRF);
            cnt += (cross && (fabsf(v.w - nxt) > THRF));
        }
        #pragma unroll
        for (int o = 16; o; o >>= 1) cnt += __shfl_xor_sync(0xffffffffu, cnt, o);
        if ((stid & 31) == 0) cw[stid >> 5] = cnt;
        BARS();
        if (stid == 0) {
            int s = 0;
            #pragma unroll
            for (int w = 0; w < 8; w++) s += cw[w];
            g_part[b][half] = s;
            __threadfence();
            unsigned old = atomicAdd(&g_flag[b], 1u);
            if (old == 1u) {
                out[Bn * 48 + b] = (float)(s + g_part[b][half ^ 1]);
                g_flag[b] = 0u;
            }
        }
    } else {
        // ================= MLP WARPS (0-7): front-find + network =================

        // ---- find first 8 discontinuities (ordered), 256-wide chunks ----
        for (int base = 0; base < Xn - 1; base += 256) {
            int i = base + tid;
            bool valid = (i < Xn - 1);
            bool disc = valid && (fabsf(d[i] - d[i + 1]) > THRF);
            unsigned m  = __ballot_sync(0xffffffffu, disc);
            unsigned vm = __ballot_sync(0xffffffffu, valid);
            if ((tid & 31) == 0) { s_wm[tid >> 5] = m; s_vm[tid >> 5] = vm; }
            BARM();
            if (tid == 0) {
                for (int w = 0; w < 8 && s_nd < 8; w++) {
                    unsigned mm = s_wm[w], vv = s_vm[w];
                    int ib = base + w * 32;
                    while (vv) {
                        int lane = __ffs(vv) - 1;
                        vv &= vv - 1;
                        int idx = ib + lane;
                        if ((mm >> lane) & 1u) {
                            if (s_nd < 8) {
                                s_idx[s_nd++] = idx;
                                if (s_nd >= 8) break;
                            }
                        } else {
                            if (s_nn < 8) s_non[s_nn++] = idx;
                        }
                    }
                }
                if (s_nd >= 8) s_done = 1;
            }
            BARM();
            if (s_done) break;
        }
        if (tid < 4) {
            int k = kbase + tid;
            int nd = s_nd;
            int i; float vf;
            if (k < nd) { i = s_idx[k]; vf = 1.0f; }
            else        { i = s_non[k - nd]; vf = 0.0f; }
            float uL = d[i], uR = d[i + 1];
            float fc = 0.5f * (cr[i] + cr[i + 1]);
            s_tk[0][tid] = uL;
            s_tk[1][tid] = uR;
            int base = b * 48;
            out[base + 16 + k] = uL;
            out[base + 24 + k] = uR;
            out[base + 32 + k] = fc;
            out[base + 40 + k] = vf;
        }
        BARM();

        // ---- input layer ----
        float pre[4];
        {
            int n = tid;
            float wv[6];
            #pragma unroll
            for (int f = 0; f < 6; f++) wv[f] = w_in[f * Hn + n];
            float bi = b_in[n];
            #pragma unroll
            for (int t = 0; t < 4; t++) {
                float uL = s_tk[0][t], uR = s_tk[1][t];
                float df = uL - uR;
                float sg = (df > 0.f) ? 1.f : ((df < 0.f) ? -1.f : 0.f);
                float p = bi;
                p = fmaf(uL, wv[0], p);
                p = fmaf(uR, wv[1], p);
                p = fmaf(df, wv[2], p);
                p = fmaf(fabsf(df), wv[3], p);
                p = fmaf(0.5f * (uL + uR), wv[4], p);
                p = fmaf(sg, wv[5], p);
                pre[t] = p;
                s_ztd[tid * 4 + t] = dup2(p);
            }
        }
        BARM();
        ln_stats_m((const float*)s_ztd, 2, s_mu, s_rs, tid);
        {
            float lg = ln_in_g[tid], lb = ln_in_b[tid];
            float4 hv;
            hv.x = gelu_f((pre[0] - s_mu[0]) * s_rs[0] * lg + lb);
            hv.y = gelu_f((pre[1] - s_mu[1]) * s_rs[1] * lg + lb);
            hv.z = gelu_f((pre[2] - s_mu[2]) * s_rs[2] * lg + lb);
            hv.w = gelu_f((pre[3] - s_mu[3]) * s_rs[3] * lg + lb);
            *(float4*)(s_h + tid * 4) = hv;
        }
        BARM();

        const int ks = tid >> 7;   // 2-way split-K group (GEMM1, head)
        const int cg = tid & 127;  // column group (GEMM1, head)

        // ---- 3 residual blocks ----
        for (int i = 0; i < 3; i++) {
            ln_stats_m(s_h, 1, s_mu, s_rs, tid);
            {
                float g = rb_ln_g[i * Hn + tid], bb = rb_ln_b[i * Hn + tid];
                float4 hv = *(const float4*)(s_h + tid * 4);
                s_ztd[tid * 4 + 0] = dup2((hv.x - s_mu[0]) * s_rs[0] * g + bb);
                s_ztd[tid * 4 + 1] = dup2((hv.y - s_mu[1]) * s_rs[1] * g + bb);
                s_ztd[tid * 4 + 2] = dup2((hv.z - s_mu[2]) * s_rs[2] * g + bb);
                s_ztd[tid * 4 + 3] = dup2((hv.w - s_mu[3]) * s_rs[3] * g + bb);
            }
            BARM();

            // ===== GEMM1: cols 4cg..4cg+3, rows ks*16..+16 per 32-row tile =====
            {
                ull acc[4][2];
                #pragma unroll
                for (int t = 0; t < 4; t++) { acc[t][0] = 0ull; acc[t][1] = 0ull; }
                #pragma unroll
                for (int t8 = 0; t8 < 8; t8++) {
                    int jglob = i * 16 + t8;
                    mbar_wait(mbf[jglob % DEPTH], (uint32_t)((jglob / DEPTH) & 1));
                    const float* cur = ringf + (jglob % DEPTH) * TILE_FLOATS;
                    #pragma unroll
                    for (int kk = 0; kk < 16; kk++) {
                        int kl = ks * 16 + kk;
                        int kg = t8 * 32 + kl;
                        ull w01, w23, z0, z1, z2, z3;
                        lds128(w01, w23, cur + kl * 512 + 4 * cg);
                        lds128(z0, z1, &s_ztd[kg * 4 + 0]);
                        lds128(z2, z3, &s_ztd[kg * 4 + 2]);
                        ffma2(acc[0][0], w01, z0); ffma2(acc[0][1], w23, z0);
                        ffma2(acc[1][0], w01, z1); ffma2(acc[1][1], w23, z1);
                        ffma2(acc[2][0], w01, z2); ffma2(acc[2][1], w23, z2);
                        ffma2(acc[3][0], w01, z3); ffma2(acc[3][1], w23, z3);
                    }
                    TILE_RELEASE(jglob);
                    TILE_ISSUE();
                }
                if (ks == 1) {
                    #pragma unroll
                    for (int t = 0; t < 4; t++) {
                        s_rd[(t * 2 + 0) * 128 + cg] = acc[t][0];
                        s_rd[(t * 2 + 1) * 128 + cg] = acc[t][1];
                    }
                }
                float4 b1v = make_float4(0.f, 0.f, 0.f, 0.f);
                if (ks == 0) b1v = *(const float4*)(rb_b1 + i * 512 + 4 * cg);
                BARM();
                if (ks == 0) {
                    #pragma unroll
                    for (int t = 0; t < 4; t++) {
                        ull a0 = addf2(acc[t][0], s_rd[(t * 2 + 0) * 128 + cg]);
                        ull a1 = addf2(acc[t][1], s_rd[(t * 2 + 1) * 128 + cg]);
                        float2 u01 = unpk(a0), u23 = unpk(a1);
                        s_zzd[(4 * cg + 0) * 4 + t] = dup2(gelu_f(u01.x + b1v.x));
                        s_zzd[(4 * cg + 1) * 4 + t] = dup2(gelu_f(u01.y + b1v.y));
                        s_zzd[(4 * cg + 2) * 4 + t] = dup2(gelu_f(u23.x + b1v.z));
                        s_zzd[(4 * cg + 3) * 4 + t] = dup2(gelu_f(u23.y + b1v.w));
                    }
                }
                BARM();
            }

            // ===== GEMM2 (GEMM1-mirror): thread (ks4=tid>>6, cg6=tid&63) ->
            //       cols 4cg6..4cg6+3, rows ks4*16..+16 per 64-row tile =====
            {
                const int ks4 = tid >> 6, cg6 = tid & 63;
                ull acc[4][2];
                #pragma unroll
                for (int t = 0; t < 4; t++) { acc[t][0] = 0ull; acc[t][1] = 0ull; }
                #pragma unroll
                for (int t8 = 0; t8 < 8; t8++) {
                    int jglob = i * 16 + 8 + t8;
                    mbar_wait(mbf[jglob % DEPTH], (uint32_t)((jglob / DEPTH) & 1));
                    const float* cur = ringf + (jglob % DEPTH) * TILE_FLOATS;
                    #pragma unroll
                    for (int kk = 0; kk < 16; kk++) {
                        int kl = ks4 * 16 + kk;
                        int kg = t8 * 64 + kl;
                        ull w01, w23, z0, z1, z2, z3;
                        lds128(w01, w23, cur + kl * 256 + 4 * cg6);
                        lds128(z0, z1, &s_zzd[kg * 4 + 0]);
                        lds128(z2, z3, &s_zzd[kg * 4 + 2]);
                        ffma2(acc[0][0], w01, z0); ffma2(acc[0][1], w23, z0);
                        ffma2(acc[1][0], w01, z1); ffma2(acc[1][1], w23, z1);
                        ffma2(acc[2][0], w01, z2); ffma2(acc[2][1], w23, z2);
                        ffma2(acc[3][0], w01, z3); ffma2(acc[3][1], w23, z3);
                    }
                    TILE_RELEASE(jglob);
                    TILE_ISSUE();
                }
                if (ks4 > 0) {
                    int km = ks4 - 1;
                    #pragma unroll
                    for (int t = 0; t < 4; t++) {
                        s_rd[(km * 8 + t * 2 + 0) * 64 + cg6] = acc[t][0];
                        s_rd[(km * 8 + t * 2 + 1) * 64 + cg6] = acc[t][1];
                    }
                }
                float4 b2v = make_float4(0.f, 0.f, 0.f, 0.f);
                if (ks4 == 0) b2v = *(const float4*)(rb_b2 + i * 256 + 4 * cg6);
                BARM();
                if (ks4 == 0) {
                    float2 u[4][2];
                    #pragma unroll
                    for (int t = 0; t < 4; t++) {
                        ull a0 = acc[t][0], a1 = acc[t][1];
                        #pragma unroll
                        for (int km = 0; km < 3; km++) {
                            a0 = addf2(a0, s_rd[(km * 8 + t * 2 + 0) * 64 + cg6]);
                            a1 = addf2(a1, s_rd[(km * 8 + t * 2 + 1) * 64 + cg6]);
                        }
                        u[t][0] = unpk(a0);
                        u[t][1] = unpk(a1);
                    }
                    int c0 = 4 * cg6;
                    float4 h0 = *(const float4*)(s_h + (c0 + 0) * 4);
                    float4 h1 = *(const float4*)(s_h + (c0 + 1) * 4);
                    float4 h2 = *(const float4*)(s_h + (c0 + 2) * 4);
                    float4 h3 = *(const float4*)(s_h + (c0 + 3) * 4);
                    h0.x += u[0][0].x + b2v.x; h0.y += u[1][0].x + b2v.x;
                    h0.z += u[2][0].x + b2v.x; h0.w += u[3][0].x + b2v.x;
                    h1.x += u[0][0].y + b2v.y; h1.y += u[1][0].y + b2v.y;
                    h1.z += u[2][0].y + b2v.y; h1.w += u[3][0].y + b2v.y;
                    h2.x += u[0][1].x + b2v.z; h2.y += u[1][1].x + b2v.z;
                    h2.z += u[2][1].x + b2v.z; h2.w += u[3][1].x + b2v.z;
                    h3.x += u[0][1].y + b2v.w; h3.y += u[1][1].y + b2v.w;
                    h3.z += u[2][1].y + b2v.w; h3.w += u[3][1].y + b2v.w;
                    *(float4*)(s_h + (c0 + 0) * 4) = h0;
                    *(float4*)(s_h + (c0 + 1) * 4) = h1;
                    *(float4*)(s_h + (c0 + 2) * 4) = h2;
                    *(float4*)(s_h + (c0 + 3) * 4) = h3;
                }
                BARM();
            }
        }

        // ---- output head ----
        ln_stats_m(s_h, 1, s_mu, s_rs, tid);
        {
            float og = out_ln_g[tid], ob = out_ln_b[tid];
            float4 hv = *(const float4*)(s_h + tid * 4);
            float4 zv;
            zv.x = (hv.x - s_mu[0]) * s_rs[0] * og + ob;
            zv.y = (hv.y - s_mu[1]) * s_rs[1] * og + ob;
            zv.z = (hv.z - s_mu[2]) * s_rs[2] * og + ob;
            zv.w = (hv.w - s_mu[3]) * s_rs[3] * og + ob;
            *(float4*)(s_zp + tid * 4) = zv;
        }
        BARM();

        // a1 = gelu(z @ out_w1 + b1): col cg, rows ks*64..+64 per 128-row tile
        {
            float a[4] = {0.f, 0.f, 0.f, 0.f};
            #pragma unroll
            for (int t8 = 0; t8 < 2; t8++) {
                int jglob = 48 + t8;
                mbar_wait(mbf[jglob % DEPTH], (uint32_t)((jglob / DEPTH) & 1));
                const float* cur = ringf + (jglob % DEPTH) * TILE_FLOATS;
                #pragma unroll 8
                for (int kk = 0; kk < 64; kk++) {
                    int kl = ks * 64 + kk;
                    int kg = t8 * 128 + kl;
                    float w = cur[kl * 128 + cg];
                    float4 z = *(const float4*)(s_zp + kg * 4);
                    a[0] = fmaf(z.x, w, a[0]);
                    a[1] = fmaf(z.y, w, a[1]);
                    a[2] = fmaf(z.z, w, a[2]);
                    a[3] = fmaf(z.w, w, a[3]);
                }
                TILE_RELEASE(jglob);
            }
            if (ks == 1) {
                #pragma unroll
                for (int t = 0; t < 4; t++)
                    s_rdf[t * 128 + cg] = a[t];
            }
            float bo = 0.f;
            if (ks == 0) bo = out_b1[cg];
            BARM();
            if (ks == 0) {
                #pragma unroll
                for (int t = 0; t < 4; t++)
                    a[t] += s_rdf[t * 128 + cg];
                *(float4*)(s_a1 + cg * 4) = make_float4(
                    gelu_f(a[0] + bo), gelu_f(a[1] + bo),
                    gelu_f(a[2] + bo), gelu_f(a[3] + bo));
            }
            BARM();
        }

        // speed = a1 @ out_w2 + out_b2: warps 0..7 -> (token, col)
        {
            int w = tid >> 5, lane = tid & 31;
            int t = w >> 1, cc = w & 1;
            float s = 0.f;
            s = fmaf(s_a1[(lane)      * 4 + t], out_w2[lane * 2 + cc],        s);
            s = fmaf(s_a1[(lane + 32) * 4 + t], out_w2[(lane + 32) * 2 + cc], s);
            s = fmaf(s_a1[(lane + 64) * 4 + t], out_w2[(lane + 64) * 2 + cc], s);
            s = fmaf(s_a1[(lane + 96) * 4 + t], out_w2[(lane + 96) * 2 + cc], s);
            #pragma unroll
            for (int o = 16; o; o >>= 1) s += __shfl_xor_sync(0xffffffffu, s, o);
            if (lane == 0)
                out[b * 48 + cc * 8 + (kbase + t)] = s + out_b2[cc];
        }
    }

    CLUSTER_SYNC_();
}

extern "C" void kernel_launch(void* const* d_in, const int* in_sizes, int n_in,
                              void* d_out, int out_size) {
    const float* x        = (const float*)d_in[0];
    const float* w_in     = (const float*)d_in[1];
    const float* b_in     = (const float*)d_in[2];
    const float* ln_in_g  = (const float*)d_in[3];
    const float* ln_in_b  = (const float*)d_in[4];
    const float* rb_ln_g  = (const float*)d_in[5];
    const float* rb_ln_b  = (const float*)d_in[6];
    const float* rb_w1    = (const float*)d_in[7];
    const float* rb_b1    = (const float*)d_in[8];
    const float* rb_w2    = (const float*)d_in[9];
    const float* rb_b2    = (const float*)d_in[10];
    const float* out_ln_g = (const float*)d_in[11];
    const float* out_ln_b = (const float*)d_in[12];
    const float* out_w1   = (const float*)d_in[13];
    const float* out_b1   = (const float*)d_in[14];
    const float* out_w2   = (const float*)d_in[15];
    const float* out_b2   = (const float*)d_in[16];
    float* out = (float*)d_out;

    // ring(128KB) + s_h(4KB) + ztd(8KB) + zzd(16KB) + zp(4KB) + a1(4KB) + rd(12KB)
    const int smem_bytes = DEPTH * TILE_FLOATS * 4 + 4096 + 8192 + 16384 + 4096 + 4096 + 12288;
    cudaFuncSetAttribute(fused_all, cudaFuncAttributeMaxDynamicSharedMemorySize, smem_bytes);

    fused_all<<<128, NT, smem_bytes>>>(x, w_in, b_in, ln_in_g, ln_in_b,
                                       rb_ln_g, rb_ln_b, rb_w1, rb_b1, rb_w2, rb_b2,
                                       out_ln_g, out_ln_b, out_w1, out_b1, out_w2, out_b2,
                                       out);
}